// round 1
// baseline (speedup 1.0000x reference)
#include <cuda_runtime.h>
#include <cuda_bf16.h>
#include <math.h>

// Problem constants
#define B_  4
#define L_  2048
#define D_  1024
#define H_  16
#define HD_ 64
#define M_  (B_ * L_)          // 8192 rows
#define QKV_N (3 * D_)         // 3072

// ---------------------------------------------------------------------------
// Scratch (device globals: allocation-free per harness rules)
// ---------------------------------------------------------------------------
__device__ float g_qkv[M_ * QKV_N];                  // [8192][3072]
__device__ float g_q[B_ * H_ * L_ * HD_];            // [b,h,l,hd]
__device__ float g_k[B_ * H_ * L_ * HD_];
__device__ float g_v[B_ * H_ * L_ * HD_];
__device__ float g_attn[M_ * D_];                    // attention out, [b,l,d]

// ---------------------------------------------------------------------------
// NT GEMM: C[M,N] = A[M,K] * W[N,K]^T   (both K-major, row-major storage)
// 128x128 tile, BK=8, 256 threads, 8x8 per thread.
// ---------------------------------------------------------------------------
#define GBM 128
#define GBN 128
#define GBK 8
#define GPAD 4

__global__ __launch_bounds__(256) void gemm_nt(
    const float* __restrict__ A, const float* __restrict__ W,
    float* __restrict__ C, int M, int N, int K)
{
    __shared__ float As[GBK][GBM + GPAD];
    __shared__ float Ws[GBK][GBN + GPAD];

    const int t = threadIdx.x;
    const int bm = blockIdx.y * GBM;
    const int bn = blockIdx.x * GBN;

    const int r = t >> 4;        // 0..15 -> rows r*8..r*8+7
    const int c = t & 15;        // 0..15 -> cols c*8..c*8+7

    const int lrow = t >> 1;            // 0..127
    const int lk   = (t & 1) * 4;       // 0 or 4

    float acc[8][8];
#pragma unroll
    for (int i = 0; i < 8; i++)
#pragma unroll
        for (int j = 0; j < 8; j++) acc[i][j] = 0.0f;

    const float* Ap = A + (size_t)(bm + lrow) * K + lk;
    const float* Wp = W + (size_t)(bn + lrow) * K + lk;

    for (int k0 = 0; k0 < K; k0 += GBK) {
        float4 av = *(const float4*)(Ap + k0);
        float4 wv = *(const float4*)(Wp + k0);
        As[lk + 0][lrow] = av.x;
        As[lk + 1][lrow] = av.y;
        As[lk + 2][lrow] = av.z;
        As[lk + 3][lrow] = av.w;
        Ws[lk + 0][lrow] = wv.x;
        Ws[lk + 1][lrow] = wv.y;
        Ws[lk + 2][lrow] = wv.z;
        Ws[lk + 3][lrow] = wv.w;
        __syncthreads();

#pragma unroll
        for (int kk = 0; kk < GBK; kk++) {
            float4 a0 = *(const float4*)&As[kk][r * 8];
            float4 a1 = *(const float4*)&As[kk][r * 8 + 4];
            float4 b0 = *(const float4*)&Ws[kk][c * 8];
            float4 b1 = *(const float4*)&Ws[kk][c * 8 + 4];
            float a[8] = {a0.x, a0.y, a0.z, a0.w, a1.x, a1.y, a1.z, a1.w};
            float b[8] = {b0.x, b0.y, b0.z, b0.w, b1.x, b1.y, b1.z, b1.w};
#pragma unroll
            for (int i = 0; i < 8; i++)
#pragma unroll
                for (int j = 0; j < 8; j++)
                    acc[i][j] = fmaf(a[i], b[j], acc[i][j]);
        }
        __syncthreads();
    }

#pragma unroll
    for (int i = 0; i < 8; i++) {
        float* Cp = C + (size_t)(bm + r * 8 + i) * N + bn + c * 8;
        *(float4*)(Cp)     = make_float4(acc[i][0], acc[i][1], acc[i][2], acc[i][3]);
        *(float4*)(Cp + 4) = make_float4(acc[i][4], acc[i][5], acc[i][6], acc[i][7]);
    }
}

// ---------------------------------------------------------------------------
// RoPE + split into [b,h,l,hd] layout. Q pre-scaled by HD^-0.5.
// One thread per (b,h,l,i) with i in [0,32): handles the (2i,2i+1) pair for
// Q and K plus two V elements.
// ---------------------------------------------------------------------------
__global__ __launch_bounds__(256) void rope_split(const float* __restrict__ qkv)
{
    int idx = blockIdx.x * blockDim.x + threadIdx.x;   // 2^22 total
    int i = idx & 31;
    int l = (idx >> 5) & (L_ - 1);
    int h = (idx >> 16) & (H_ - 1);
    int b = idx >> 20;

    const float* row = qkv + (size_t)(b * L_ + l) * QKV_N;

    float inv = powf(10000.0f, -(float)(2 * i) * (1.0f / (float)HD_));
    float ang = (float)l * inv;
    float cs = cosf(ang);
    float sn = sinf(ang);

    int off = h * HD_ + 2 * i;
    float q1 = row[off],        q2 = row[off + 1];
    float k1 = row[D_ + off],   k2 = row[D_ + off + 1];

    size_t o = ((size_t)((b * H_ + h) * L_ + l)) * HD_;
    const float qscale = 0.125f;  // HD^-0.5 = 1/8
    g_q[o + i]       = (q1 * cs - q2 * sn) * qscale;
    g_q[o + i + 32]  = (q1 * sn + q2 * cs) * qscale;
    g_k[o + i]       = k1 * cs - k2 * sn;
    g_k[o + i + 32]  = k1 * sn + k2 * cs;

    g_v[o + i]       = row[2 * D_ + h * HD_ + i];
    g_v[o + i + 32]  = row[2 * D_ + h * HD_ + i + 32];
}

// ---------------------------------------------------------------------------
// Flash attention (fp32, online softmax).
// Grid: (L/64, H, B). Block: 256 threads. Each CTA: 64 queries x full K loop.
// Thread (r=t/16, c=t%15) owns a 4x4 patch.
// Dynamic smem: Qt[64][68] (d-major), KPt[64][68] (Kt then Pt), Vs[64][68].
// ---------------------------------------------------------------------------
#define APAD 4
#define AST  (64 + APAD)   // 68

__global__ __launch_bounds__(256) void attn_kernel(float* __restrict__ out)
{
    extern __shared__ float sm[];
    float* Qt  = sm;                 // Qt[d][qrow]
    float* KPt = sm + 64 * AST;      // Kt[d][krow]  /  Pt[kcol][qrow]
    float* Vs  = sm + 2 * 64 * AST;  // Vs[krow][d]

    const int qblk = blockIdx.x;
    const int h = blockIdx.y;
    const int b = blockIdx.z;
    const int t = threadIdx.x;
    const int r = t >> 4;   // 0..15
    const int c = t & 15;   // 0..15

    const size_t base = (size_t)((b * H_ + h)) * L_ * HD_;
    const float* Qg = g_q + base + (size_t)qblk * 64 * HD_;
    const float* Kg = g_k + base;
    const float* Vg = g_v + base;

    // Load Q block transposed into smem (stays for the whole kernel)
    {
        const int lrow = t >> 2;
        const int ld0  = (t & 3) << 2;
#pragma unroll
        for (int dch = 0; dch < 64; dch += 16) {
            int ld = ld0 + dch;
            float4 v = *(const float4*)&Qg[lrow * HD_ + ld];
            Qt[(ld + 0) * AST + lrow] = v.x;
            Qt[(ld + 1) * AST + lrow] = v.y;
            Qt[(ld + 2) * AST + lrow] = v.z;
            Qt[(ld + 3) * AST + lrow] = v.w;
        }
    }

    float m[4], l[4], o[4][4];
#pragma unroll
    for (int i = 0; i < 4; i++) {
        m[i] = -3.0e38f;
        l[i] = 0.0f;
#pragma unroll
        for (int j = 0; j < 4; j++) o[i][j] = 0.0f;
    }

    for (int kb = 0; kb < L_ / 64; kb++) {
        __syncthreads();   // previous iter's PV reads done before overwrite
        {
            const int lrow = t >> 2;
            const int ld0  = (t & 3) << 2;
#pragma unroll
            for (int dch = 0; dch < 64; dch += 16) {
                int ld = ld0 + dch;
                float4 kv = *(const float4*)&Kg[(kb * 64 + lrow) * HD_ + ld];
                KPt[(ld + 0) * AST + lrow] = kv.x;
                KPt[(ld + 1) * AST + lrow] = kv.y;
                KPt[(ld + 2) * AST + lrow] = kv.z;
                KPt[(ld + 3) * AST + lrow] = kv.w;
                float4 vv = *(const float4*)&Vg[(kb * 64 + lrow) * HD_ + ld];
                *(float4*)&Vs[lrow * AST + ld] = vv;
            }
        }
        __syncthreads();

        // S = Q * K^T  (scale already folded into Q)
        float s[4][4];
#pragma unroll
        for (int i = 0; i < 4; i++)
#pragma unroll
            for (int j = 0; j < 4; j++) s[i][j] = 0.0f;

#pragma unroll
        for (int d = 0; d < 64; d++) {
            float4 a = *(const float4*)&Qt[d * AST + r * 4];
            float4 bb = *(const float4*)&KPt[d * AST + c * 4];
            float av[4] = {a.x, a.y, a.z, a.w};
            float bv[4] = {bb.x, bb.y, bb.z, bb.w};
#pragma unroll
            for (int i = 0; i < 4; i++)
#pragma unroll
                for (int j = 0; j < 4; j++)
                    s[i][j] = fmaf(av[i], bv[j], s[i][j]);
        }

        // Online softmax update (row stats via 16-lane shfl groups)
        float ps[4][4];
#pragma unroll
        for (int i = 0; i < 4; i++) {
            float tm = fmaxf(fmaxf(s[i][0], s[i][1]), fmaxf(s[i][2], s[i][3]));
#pragma unroll
            for (int off = 8; off >= 1; off >>= 1)
                tm = fmaxf(tm, __shfl_xor_sync(0xffffffffu, tm, off));
            float nm = fmaxf(m[i], tm);
            float sum = 0.0f;
#pragma unroll
            for (int j = 0; j < 4; j++) {
                ps[i][j] = __expf(s[i][j] - nm);
                sum += ps[i][j];
            }
#pragma unroll
            for (int off = 8; off >= 1; off >>= 1)
                sum += __shfl_xor_sync(0xffffffffu, sum, off);
            float f = __expf(m[i] - nm);
            l[i] = l[i] * f + sum;
            m[i] = nm;
#pragma unroll
            for (int j = 0; j < 4; j++) o[i][j] *= f;
        }

        __syncthreads();   // everyone finished reading Kt
        // Stage P transposed: Pt[kcol][qrow]
#pragma unroll
        for (int j = 0; j < 4; j++)
#pragma unroll
            for (int i = 0; i < 4; i++)
                KPt[(c * 4 + j) * AST + (r * 4 + i)] = ps[i][j];
        __syncthreads();

        // O += P * V
#pragma unroll
        for (int kk = 0; kk < 64; kk++) {
            float4 a = *(const float4*)&KPt[kk * AST + r * 4];
            float4 bv4 = *(const float4*)&Vs[kk * AST + c * 4];
            float av[4] = {a.x, a.y, a.z, a.w};
            float bv[4] = {bv4.x, bv4.y, bv4.z, bv4.w};
#pragma unroll
            for (int i = 0; i < 4; i++)
#pragma unroll
                for (int j = 0; j < 4; j++)
                    o[i][j] = fmaf(av[i], bv[j], o[i][j]);
        }
    }

    // Write normalized output in [b,l,d] layout
#pragma unroll
    for (int i = 0; i < 4; i++) {
        float inv_l = 1.0f / l[i];
        size_t row = (size_t)(b * L_ + qblk * 64 + r * 4 + i);
        float* op = out + row * D_ + h * HD_ + c * 4;
        *(float4*)op = make_float4(o[i][0] * inv_l, o[i][1] * inv_l,
                                   o[i][2] * inv_l, o[i][3] * inv_l);
    }
}

// ---------------------------------------------------------------------------
// Launcher
// ---------------------------------------------------------------------------
extern "C" void kernel_launch(void* const* d_in, const int* in_sizes, int n_in,
                              void* d_out, int out_size)
{
    const float* x     = (const float*)d_in[0];   // [B,L,D]
    const float* Wqkv  = (const float*)d_in[1];   // [3D,D]
    const float* Wproj = (const float*)d_in[2];   // [D,D]
    float* out = (float*)d_out;                   // [B,L,D]

    float *qkv_p, *attn_p;
    cudaGetSymbolAddress((void**)&qkv_p, g_qkv);
    cudaGetSymbolAddress((void**)&attn_p, g_attn);

    const int smem_attn = 3 * 64 * AST * sizeof(float);  // 52224 B
    cudaFuncSetAttribute(attn_kernel,
                         cudaFuncAttributeMaxDynamicSharedMemorySize, smem_attn);

    // 1) QKV projection: [8192,3072] = x[8192,1024] * Wqkv^T
    gemm_nt<<<dim3(QKV_N / GBN, M_ / GBM), 256>>>(x, Wqkv, qkv_p, M_, QKV_N, D_);

    // 2) RoPE + split to [b,h,l,hd]
    rope_split<<<(B_ * H_ * L_ * 32) / 256, 256>>>(qkv_p);

    // 3) Attention
    attn_kernel<<<dim3(L_ / 64, H_, B_), 256, smem_attn>>>(attn_p);

    // 4) Output projection
    gemm_nt<<<dim3(D_ / GBN, M_ / GBM), 256>>>(attn_p, Wproj, out, M_, D_, D_);
}

// round 3
// speedup vs baseline: 1.1731x; 1.1731x over previous
#include <cuda_runtime.h>
#include <cuda_bf16.h>
#include <math.h>

// Problem constants
#define B_  4
#define L_  2048
#define D_  1024
#define H_  16
#define HD_ 64
#define M_  (B_ * L_)          // 8192
#define QKV_N (3 * D_)         // 3072

// ---------------------------------------------------------------------------
// Scratch (device globals)
// ---------------------------------------------------------------------------
__device__ float g_qkv[M_ * QKV_N];
__device__ float g_q[B_ * H_ * L_ * HD_];            // [b,h,l,hd]
__device__ float g_k[B_ * H_ * L_ * HD_];
__device__ float g_v[B_ * H_ * L_ * HD_];
__device__ float g_attn[M_ * D_];                    // [b,l,d]

// ---------------------------------------------------------------------------
// Helpers
// ---------------------------------------------------------------------------
__device__ __forceinline__ float to_tf32(float x) {
    unsigned u;
    asm("cvt.rna.tf32.f32 %0, %1;" : "=r"(u) : "f"(x));
    return __uint_as_float(u);
}

// 3xTF32 split: x ~= hi + lo, both tf32-representable.
__device__ __forceinline__ void split32(float x, unsigned& hi, unsigned& lo) {
    float h = to_tf32(x);
    hi = __float_as_uint(h);
    lo = __float_as_uint(to_tf32(x - h));
}

#define MMA_TF32(d, a, b)                                                     \
    asm volatile(                                                             \
        "mma.sync.aligned.m16n8k8.row.col.f32.tf32.tf32.f32 "                 \
        "{%0,%1,%2,%3}, {%4,%5,%6,%7}, {%8,%9}, {%0,%1,%2,%3};"               \
        : "+f"((d)[0]), "+f"((d)[1]), "+f"((d)[2]), "+f"((d)[3])              \
        : "r"((a)[0]), "r"((a)[1]), "r"((a)[2]), "r"((a)[3]),                 \
          "r"((b)[0]), "r"((b)[1]))

#define CP_ASYNC16(smem_u32, gptr)                                            \
    asm volatile("cp.async.cg.shared.global [%0], [%1], 16;"                  \
                 :: "r"(smem_u32), "l"(gptr))
#define CP_COMMIT()  asm volatile("cp.async.commit_group;" ::: "memory")
#define CP_WAIT0()   asm volatile("cp.async.wait_group 0;" ::: "memory")

// ---------------------------------------------------------------------------
// 3xTF32 NT GEMM: C[M,N] = A[M,K] * W[N,K]^T (row-major A and W).
// CTA 128x128x32, 256 threads (8 warps: 2m x 4n), warp tile 64x32.
// Smem stride 36 (==4 mod 32) -> conflict-free TF32 fragment loads.
// ---------------------------------------------------------------------------
#define GST 36

__global__ __launch_bounds__(256, 2) void gemm_tf32(
    const float* __restrict__ A, const float* __restrict__ W,
    float* __restrict__ C, int M, int N, int K)
{
    extern __shared__ float sm[];
    float* As = sm;                    // [2][128*GST]
    float* Ws = sm + 2 * 128 * GST;    // [2][128*GST]

    const int t = threadIdx.x;
    const int w = t >> 5, lane = t & 31;
    const int g = lane >> 2, qd = lane & 3;
    const int wm = (w & 1) * 64;
    const int wn = (w >> 1) * 32;
    const int bm = blockIdx.y * 128, bn = blockIdx.x * 128;

    const int lrow = t >> 1;
    const int lk4  = (t & 1) * 16;

    const float* Ag = A + (size_t)(bm + lrow) * K + lk4;
    const float* Wg = W + (size_t)(bn + lrow) * K + lk4;
    const unsigned sa_base = (unsigned)__cvta_generic_to_shared(As + lrow * GST + lk4);
    const unsigned sw_base = (unsigned)__cvta_generic_to_shared(Ws + lrow * GST + lk4);
    const unsigned stage_bytes = 128 * GST * 4;

    float acc[4][4][4];
#pragma unroll
    for (int mi = 0; mi < 4; mi++)
#pragma unroll
        for (int ni = 0; ni < 4; ni++)
#pragma unroll
            for (int k = 0; k < 4; k++) acc[mi][ni][k] = 0.0f;

    // issue stage 0
    {
#pragma unroll
        for (int i = 0; i < 4; i++) {
            CP_ASYNC16(sa_base + i * 16, Ag + i * 4);
            CP_ASYNC16(sw_base + i * 16, Wg + i * 4);
        }
        CP_COMMIT();
    }

    const int NK = K >> 5;
    for (int ks = 0; ks < NK; ks++) {
        CP_WAIT0();
        __syncthreads();
        if (ks + 1 < NK) {
            int st = (ks + 1) & 1;
            int k0 = (ks + 1) * 32;
#pragma unroll
            for (int i = 0; i < 4; i++) {
                CP_ASYNC16(sa_base + st * stage_bytes + i * 16, Ag + k0 + i * 4);
                CP_ASYNC16(sw_base + st * stage_bytes + i * 16, Wg + k0 + i * 4);
            }
            CP_COMMIT();
        }
        const float* as = As + (ks & 1) * 128 * GST;
        const float* ws = Ws + (ks & 1) * 128 * GST;

#pragma unroll
        for (int kk = 0; kk < 4; kk++) {
            const int k0 = kk * 8;
            unsigned ah[4][4], al[4][4];
#pragma unroll
            for (int mi = 0; mi < 4; mi++) {
                const float* ap = as + (wm + mi * 16 + g) * GST + k0 + qd;
                split32(ap[0],            ah[mi][0], al[mi][0]);
                split32(ap[8 * GST],      ah[mi][1], al[mi][1]);
                split32(ap[4],            ah[mi][2], al[mi][2]);
                split32(ap[8 * GST + 4],  ah[mi][3], al[mi][3]);
            }
#pragma unroll
            for (int ni = 0; ni < 4; ni++) {
                const float* bp = ws + (wn + ni * 8 + g) * GST + k0 + qd;
                unsigned bh[2], bl[2];
                split32(bp[0], bh[0], bl[0]);
                split32(bp[4], bh[1], bl[1]);
#pragma unroll
                for (int mi = 0; mi < 4; mi++) {
                    MMA_TF32(acc[mi][ni], ah[mi], bh);
                    MMA_TF32(acc[mi][ni], al[mi], bh);
                    MMA_TF32(acc[mi][ni], ah[mi], bl);
                }
            }
        }
    }

    // epilogue
#pragma unroll
    for (int mi = 0; mi < 4; mi++)
#pragma unroll
        for (int rr = 0; rr < 2; rr++) {
            int row = bm + wm + mi * 16 + g + rr * 8;
            float* Cp = C + (size_t)row * N + bn + wn + 2 * qd;
#pragma unroll
            for (int ni = 0; ni < 4; ni++) {
                float2 v = make_float2(acc[mi][ni][2 * rr], acc[mi][ni][2 * rr + 1]);
                *(float2*)(Cp + ni * 8) = v;
            }
        }
}

// ---------------------------------------------------------------------------
// RoPE + split to [b,h,l,hd]; Q pre-scaled by HD^-0.5. Full fp32 outputs.
// ---------------------------------------------------------------------------
__global__ __launch_bounds__(256) void rope_split(const float* __restrict__ qkv)
{
    int idx = blockIdx.x * blockDim.x + threadIdx.x;
    int i = idx & 31;
    int l = (idx >> 5) & (L_ - 1);
    int h = (idx >> 16) & (H_ - 1);
    int b = idx >> 20;

    const float* row = qkv + (size_t)(b * L_ + l) * QKV_N;

    float inv = powf(10000.0f, -(float)(2 * i) * (1.0f / (float)HD_));
    float ang = (float)l * inv;
    float cs = cosf(ang);
    float sn = sinf(ang);

    int off = h * HD_ + 2 * i;
    float q1 = row[off],      q2 = row[off + 1];
    float k1 = row[D_ + off], k2 = row[D_ + off + 1];

    size_t o = ((size_t)((b * H_ + h) * L_ + l)) * HD_;
    const float qscale = 0.125f;
    g_q[o + i]      = (q1 * cs - q2 * sn) * qscale;
    g_q[o + i + 32] = (q1 * sn + q2 * cs) * qscale;
    g_k[o + i]      = k1 * cs - k2 * sn;
    g_k[o + i + 32] = k1 * sn + k2 * cs;
    g_v[o + i]      = row[2 * D_ + h * HD_ + i];
    g_v[o + i + 32] = row[2 * D_ + h * HD_ + i + 32];
}

// ---------------------------------------------------------------------------
// Flash attention, 3xTF32 mma. CTA = 64 queries, 4 warps, each warp owns
// 16 q-rows x full 64 kv-cols (row stats intra-warp). K/V chunks of 64,
// cp.async double-buffered.
// ---------------------------------------------------------------------------
#define QST 68
#define VST 72

__global__ __launch_bounds__(128) void attn_tf32(float* __restrict__ out)
{
    extern __shared__ float sm[];
    float* Qs  = sm;                       // 64*QST
    float* Ps  = Qs + 64 * QST;            // 64*QST
    float* Ks0 = Ps + 64 * QST;            // 2 stages * 64*QST
    float* Vs0 = Ks0 + 2 * 64 * QST;       // 2 stages * 64*VST

    const int qblk = blockIdx.x, h = blockIdx.y, b = blockIdx.z;
    const int t = threadIdx.x, w = t >> 5, lane = t & 31;
    const int g = lane >> 2, qd = lane & 3;

    const size_t base = ((size_t)(b * H_ + h)) * L_ * HD_;
    const float* Qg = g_q + base + (size_t)qblk * 64 * HD_;
    const float* Kg = g_k + base;
    const float* Vg = g_v + base;

    const int lrow = t >> 1;
    const int seg  = (t & 1) * 32;
    const unsigned ks_base = (unsigned)__cvta_generic_to_shared(Ks0 + lrow * QST + seg);
    const unsigned vs_base = (unsigned)__cvta_generic_to_shared(Vs0 + lrow * VST + seg);
    const unsigned kstage = 64 * QST * 4, vstage = 64 * VST * 4;

    // issue KV chunk 0
    {
        const float* kg = Kg + (size_t)lrow * HD_ + seg;
        const float* vg = Vg + (size_t)lrow * HD_ + seg;
#pragma unroll
        for (int i = 0; i < 8; i++) {
            CP_ASYNC16(ks_base + i * 16, kg + i * 4);
            CP_ASYNC16(vs_base + i * 16, vg + i * 4);
        }
        CP_COMMIT();
    }

    // load Q into smem
#pragma unroll
    for (int i = 0; i < 8; i++) {
        float4 v = *(const float4*)(Qg + lrow * HD_ + seg + i * 4);
        *(float4*)(Qs + lrow * QST + seg + i * 4) = v;
    }

    float mrow[2] = {-3.0e38f, -3.0e38f};
    float lrow_s[2] = {0.0f, 0.0f};
    float oacc[8][4];
#pragma unroll
    for (int ni = 0; ni < 8; ni++)
#pragma unroll
        for (int k = 0; k < 4; k++) oacc[ni][k] = 0.0f;

    const int NKB = L_ / 64;
    for (int kb = 0; kb < NKB; kb++) {
        CP_WAIT0();
        __syncthreads();
        if (kb + 1 < NKB) {
            int st = (kb + 1) & 1;
            const float* kg = Kg + (size_t)((kb + 1) * 64 + lrow) * HD_ + seg;
            const float* vg = Vg + (size_t)((kb + 1) * 64 + lrow) * HD_ + seg;
#pragma unroll
            for (int i = 0; i < 8; i++) {
                CP_ASYNC16(ks_base + st * kstage + i * 16, kg + i * 4);
                CP_ASYNC16(vs_base + st * vstage + i * 16, vg + i * 4);
            }
            CP_COMMIT();
        }
        const float* ks = Ks0 + (kb & 1) * 64 * QST;
        const float* vs = Vs0 + (kb & 1) * 64 * VST;

        // S = Q * K^T (3xTF32)
        float sacc[8][4];
#pragma unroll
        for (int ni = 0; ni < 8; ni++)
#pragma unroll
            for (int k = 0; k < 4; k++) sacc[ni][k] = 0.0f;

#pragma unroll
        for (int kk = 0; kk < 8; kk++) {
            unsigned qh[4], ql[4];
            const float* ap = Qs + (w * 16 + g) * QST + kk * 8 + qd;
            split32(ap[0],            qh[0], ql[0]);
            split32(ap[8 * QST],      qh[1], ql[1]);
            split32(ap[4],            qh[2], ql[2]);
            split32(ap[8 * QST + 4],  qh[3], ql[3]);
#pragma unroll
            for (int ni = 0; ni < 8; ni++) {
                const float* bp = ks + (ni * 8 + g) * QST + kk * 8 + qd;
                unsigned kh[2], kl[2];
                split32(bp[0], kh[0], kl[0]);
                split32(bp[4], kh[1], kl[1]);
                MMA_TF32(sacc[ni], qh, kh);
                MMA_TF32(sacc[ni], ql, kh);
                MMA_TF32(sacc[ni], qh, kl);
            }
        }

        // online softmax (rows: w*16 + g + 8*rr)
#pragma unroll
        for (int rr = 0; rr < 2; rr++) {
            float tm = -3.0e38f;
#pragma unroll
            for (int ni = 0; ni < 8; ni++)
                tm = fmaxf(tm, fmaxf(sacc[ni][2 * rr], sacc[ni][2 * rr + 1]));
            tm = fmaxf(tm, __shfl_xor_sync(0xffffffffu, tm, 1));
            tm = fmaxf(tm, __shfl_xor_sync(0xffffffffu, tm, 2));
            float nm = fmaxf(mrow[rr], tm);
            float sum = 0.0f;
#pragma unroll
            for (int ni = 0; ni < 8; ni++) {
                float p0 = __expf(sacc[ni][2 * rr] - nm);
                float p1 = __expf(sacc[ni][2 * rr + 1] - nm);
                sacc[ni][2 * rr] = p0;
                sacc[ni][2 * rr + 1] = p1;
                sum += p0 + p1;
            }
            sum += __shfl_xor_sync(0xffffffffu, sum, 1);
            sum += __shfl_xor_sync(0xffffffffu, sum, 2);
            float f = __expf(mrow[rr] - nm);
            lrow_s[rr] = lrow_s[rr] * f + sum;
            mrow[rr] = nm;
#pragma unroll
            for (int ni = 0; ni < 8; ni++) {
                oacc[ni][2 * rr] *= f;
                oacc[ni][2 * rr + 1] *= f;
            }
        }

        // stage P to smem (full fp32)
#pragma unroll
        for (int ni = 0; ni < 8; ni++) {
            float* pp = Ps + (w * 16 + g) * QST + ni * 8 + 2 * qd;
            pp[0] = sacc[ni][0];
            pp[1] = sacc[ni][1];
            pp[8 * QST] = sacc[ni][2];
            pp[8 * QST + 1] = sacc[ni][3];
        }
        __syncthreads();

        // O += P * V (3xTF32)
#pragma unroll
        for (int kk = 0; kk < 8; kk++) {
            unsigned ph[4], pl[4];
            const float* ap = Ps + (w * 16 + g) * QST + kk * 8 + qd;
            split32(ap[0],            ph[0], pl[0]);
            split32(ap[8 * QST],      ph[1], pl[1]);
            split32(ap[4],            ph[2], pl[2]);
            split32(ap[8 * QST + 4],  ph[3], pl[3]);
#pragma unroll
            for (int ni = 0; ni < 8; ni++) {
                const float* bp = vs + (kk * 8 + qd) * VST + ni * 8 + g;
                unsigned vh[2], vl[2];
                split32(bp[0],       vh[0], vl[0]);
                split32(bp[4 * VST], vh[1], vl[1]);
                MMA_TF32(oacc[ni], ph, vh);
                MMA_TF32(oacc[ni], pl, vh);
                MMA_TF32(oacc[ni], ph, vl);
            }
        }
    }

    // epilogue: normalize and write [b,l,d]
#pragma unroll
    for (int rr = 0; rr < 2; rr++) {
        int row = qblk * 64 + w * 16 + g + rr * 8;
        float inv = 1.0f / lrow_s[rr];
        float* op = out + (size_t)(b * L_ + row) * D_ + h * HD_ + 2 * qd;
#pragma unroll
        for (int ni = 0; ni < 8; ni++) {
            float2 v = make_float2(oacc[ni][2 * rr] * inv, oacc[ni][2 * rr + 1] * inv);
            *(float2*)(op + ni * 8) = v;
        }
    }
}

// ---------------------------------------------------------------------------
// Launcher
// ---------------------------------------------------------------------------
extern "C" void kernel_launch(void* const* d_in, const int* in_sizes, int n_in,
                              void* d_out, int out_size)
{
    const float* x     = (const float*)d_in[0];
    const float* Wqkv  = (const float*)d_in[1];
    const float* Wproj = (const float*)d_in[2];
    float* out = (float*)d_out;

    float *qkv_p, *attn_p;
    cudaGetSymbolAddress((void**)&qkv_p, g_qkv);
    cudaGetSymbolAddress((void**)&attn_p, g_attn);

    const int smem_gemm = 4 * 128 * GST * sizeof(float);                               // 73728
    const int smem_attn = (2 * 64 * QST + 2 * 64 * QST + 2 * 64 * VST) * sizeof(float); // 106496
    cudaFuncSetAttribute(gemm_tf32, cudaFuncAttributeMaxDynamicSharedMemorySize, smem_gemm);
    cudaFuncSetAttribute(attn_tf32, cudaFuncAttributeMaxDynamicSharedMemorySize, smem_attn);

    // 1) QKV projection
    gemm_tf32<<<dim3(QKV_N / 128, M_ / 128), 256, smem_gemm>>>(x, Wqkv, qkv_p, M_, QKV_N, D_);

    // 2) RoPE + split
    rope_split<<<(B_ * H_ * L_ * 32) / 256, 256>>>(qkv_p);

    // 3) Attention
    attn_tf32<<<dim3(L_ / 64, H_, B_), 128, smem_attn>>>(attn_p);

    // 4) Output projection
    gemm_tf32<<<dim3(D_ / 128, M_ / 128), 256, smem_gemm>>>(attn_p, Wproj, out, M_, D_, D_);
}

// round 4
// speedup vs baseline: 1.8822x; 1.6045x over previous
#include <cuda_runtime.h>
#include <cuda_bf16.h>
#include <math.h>

// Problem constants
#define B_  4
#define L_  2048
#define D_  1024
#define H_  16
#define HD_ 64
#define M_  (B_ * L_)          // 8192
#define QKV_N (3 * D_)         // 3072

// ---------------------------------------------------------------------------
// Scratch (device globals)
// ---------------------------------------------------------------------------
__device__ float g_qkv[M_ * QKV_N];
__device__ float g_q[B_ * H_ * L_ * HD_];            // [b,h,l,hd]
__device__ float g_k[B_ * H_ * L_ * HD_];
__device__ float g_v[B_ * H_ * L_ * HD_];
__device__ float g_attn[M_ * D_];                    // [b,l,d]

// ---------------------------------------------------------------------------
// Helpers
// ---------------------------------------------------------------------------
// Split a pair of fp32 into packed bf16 hi and lo: x ~= hi + lo.
// Packs element0 into the LOW 16 bits (even-k slot of the mma fragment).
__device__ __forceinline__ void split2(float x0, float x1,
                                       unsigned& hi, unsigned& lo) {
    unsigned h;
    asm("cvt.rn.bf16x2.f32 %0, %1, %2;" : "=r"(h) : "f"(x1), "f"(x0));
    float h0 = __uint_as_float(h << 16);
    float h1 = __uint_as_float(h & 0xffff0000u);
    float r0 = x0 - h0;
    float r1 = x1 - h1;
    unsigned l;
    asm("cvt.rn.bf16x2.f32 %0, %1, %2;" : "=r"(l) : "f"(r1), "f"(r0));
    hi = h; lo = l;
}

#define MMA_BF16(d, a, b)                                                     \
    asm volatile(                                                             \
        "mma.sync.aligned.m16n8k16.row.col.f32.bf16.bf16.f32 "                \
        "{%0,%1,%2,%3}, {%4,%5,%6,%7}, {%8,%9}, {%0,%1,%2,%3};"               \
        : "+f"((d)[0]), "+f"((d)[1]), "+f"((d)[2]), "+f"((d)[3])              \
        : "r"((a)[0]), "r"((a)[1]), "r"((a)[2]), "r"((a)[3]),                 \
          "r"((b)[0]), "r"((b)[1]))

#define CP_ASYNC16(smem_u32, gptr)                                            \
    asm volatile("cp.async.cg.shared.global [%0], [%1], 16;"                  \
                 :: "r"(smem_u32), "l"(gptr))
#define CP_COMMIT()  asm volatile("cp.async.commit_group;" ::: "memory")
#define CP_WAIT0()   asm volatile("cp.async.wait_group 0;" ::: "memory")

// ---------------------------------------------------------------------------
// 3-term bf16 NT GEMM: C[M,N] = A[M,K] * W[N,K]^T (row-major A and W).
// CTA 128x128x32, 256 threads (8 warps: 2m x 4n), warp tile 64x32.
// fp32 smem tiles, stride 40 (==8 mod 32): conflict-free float2 frag loads.
// ---------------------------------------------------------------------------
#define GST 40

__global__ __launch_bounds__(256, 2) void gemm_b3(
    const float* __restrict__ A, const float* __restrict__ W,
    float* __restrict__ C, int M, int N, int K)
{
    extern __shared__ float sm[];
    float* As = sm;                    // [2][128*GST]
    float* Ws = sm + 2 * 128 * GST;    // [2][128*GST]

    const int t = threadIdx.x;
    const int w = t >> 5, lane = t & 31;
    const int g = lane >> 2, qd = lane & 3;
    const int wm = (w & 1) * 64;
    const int wn = (w >> 1) * 32;
    const int bm = blockIdx.y * 128, bn = blockIdx.x * 128;

    const int lrow = t >> 1;
    const int lk4  = (t & 1) * 16;

    const float* Ag = A + (size_t)(bm + lrow) * K + lk4;
    const float* Wg = W + (size_t)(bn + lrow) * K + lk4;
    const unsigned sa_base = (unsigned)__cvta_generic_to_shared(As + lrow * GST + lk4);
    const unsigned sw_base = (unsigned)__cvta_generic_to_shared(Ws + lrow * GST + lk4);
    const unsigned stage_bytes = 128 * GST * 4;

    float acc[4][4][4];
#pragma unroll
    for (int mi = 0; mi < 4; mi++)
#pragma unroll
        for (int ni = 0; ni < 4; ni++)
#pragma unroll
            for (int k = 0; k < 4; k++) acc[mi][ni][k] = 0.0f;

    // issue stage 0
    {
#pragma unroll
        for (int i = 0; i < 4; i++) {
            CP_ASYNC16(sa_base + i * 16, Ag + i * 4);
            CP_ASYNC16(sw_base + i * 16, Wg + i * 4);
        }
        CP_COMMIT();
    }

    const int NK = K >> 5;
    for (int ks = 0; ks < NK; ks++) {
        CP_WAIT0();
        __syncthreads();
        if (ks + 1 < NK) {
            int st = (ks + 1) & 1;
            int k0 = (ks + 1) * 32;
#pragma unroll
            for (int i = 0; i < 4; i++) {
                CP_ASYNC16(sa_base + st * stage_bytes + i * 16, Ag + k0 + i * 4);
                CP_ASYNC16(sw_base + st * stage_bytes + i * 16, Wg + k0 + i * 4);
            }
            CP_COMMIT();
        }
        const float* as = As + (ks & 1) * 128 * GST;
        const float* ws = Ws + (ks & 1) * 128 * GST;

#pragma unroll
        for (int kk = 0; kk < 2; kk++) {           // two 16-K chunks
            const int k0 = kk * 16;
            unsigned ah[4][4], al[4][4];
#pragma unroll
            for (int mi = 0; mi < 4; mi++) {
                const float* ap = as + (wm + mi * 16 + g) * GST + k0 + 2 * qd;
                float2 x0 = *(const float2*)(ap);
                float2 x1 = *(const float2*)(ap + 8 * GST);
                float2 x2 = *(const float2*)(ap + 8);
                float2 x3 = *(const float2*)(ap + 8 * GST + 8);
                split2(x0.x, x0.y, ah[mi][0], al[mi][0]);
                split2(x1.x, x1.y, ah[mi][1], al[mi][1]);
                split2(x2.x, x2.y, ah[mi][2], al[mi][2]);
                split2(x3.x, x3.y, ah[mi][3], al[mi][3]);
            }
#pragma unroll
            for (int ni = 0; ni < 4; ni++) {
                const float* bp = ws + (wn + ni * 8 + g) * GST + k0 + 2 * qd;
                float2 y0 = *(const float2*)(bp);
                float2 y1 = *(const float2*)(bp + 8);
                unsigned bh[2], bl[2];
                split2(y0.x, y0.y, bh[0], bl[0]);
                split2(y1.x, y1.y, bh[1], bl[1]);
#pragma unroll
                for (int mi = 0; mi < 4; mi++) {
                    MMA_BF16(acc[mi][ni], ah[mi], bh);
                    MMA_BF16(acc[mi][ni], al[mi], bh);
                    MMA_BF16(acc[mi][ni], ah[mi], bl);
                }
            }
        }
    }

    // epilogue
#pragma unroll
    for (int mi = 0; mi < 4; mi++)
#pragma unroll
        for (int rr = 0; rr < 2; rr++) {
            int row = bm + wm + mi * 16 + g + rr * 8;
            float* Cp = C + (size_t)row * N + bn + wn + 2 * qd;
#pragma unroll
            for (int ni = 0; ni < 4; ni++) {
                float2 v = make_float2(acc[mi][ni][2 * rr], acc[mi][ni][2 * rr + 1]);
                *(float2*)(Cp + ni * 8) = v;
            }
        }
}

// ---------------------------------------------------------------------------
// RoPE + split to [b,h,l,hd]; Q pre-scaled by HD^-0.5. Full fp32 outputs.
// ---------------------------------------------------------------------------
__global__ __launch_bounds__(256) void rope_split(const float* __restrict__ qkv)
{
    int idx = blockIdx.x * blockDim.x + threadIdx.x;
    int i = idx & 31;
    int l = (idx >> 5) & (L_ - 1);
    int h = (idx >> 16) & (H_ - 1);
    int b = idx >> 20;

    const float* row = qkv + (size_t)(b * L_ + l) * QKV_N;

    float inv = powf(10000.0f, -(float)(2 * i) * (1.0f / (float)HD_));
    float ang = (float)l * inv;
    float cs = cosf(ang);
    float sn = sinf(ang);

    int off = h * HD_ + 2 * i;
    float q1 = row[off],      q2 = row[off + 1];
    float k1 = row[D_ + off], k2 = row[D_ + off + 1];

    size_t o = ((size_t)((b * H_ + h) * L_ + l)) * HD_;
    const float qscale = 0.125f;
    g_q[o + i]      = (q1 * cs - q2 * sn) * qscale;
    g_q[o + i + 32] = (q1 * sn + q2 * cs) * qscale;
    g_k[o + i]      = k1 * cs - k2 * sn;
    g_k[o + i + 32] = k1 * sn + k2 * cs;
    g_v[o + i]      = row[2 * D_ + h * HD_ + i];
    g_v[o + i + 32] = row[2 * D_ + h * HD_ + i + 32];
}

// ---------------------------------------------------------------------------
// Flash attention, 3-term bf16 mma. CTA = 64 queries, 4 warps, each warp
// owns 16 q-rows x all 64 kv-cols (row stats intra-warp). K/V chunks of 64,
// cp.async double-buffered.
// Strides: QST=72 (==8 mod 32) for Qs/Ps/Ks (float2 frag loads),
//          VST=68 (==4 mod 32) for Vs (scalar B loads conflict-free).
// ---------------------------------------------------------------------------
#define QST 72
#define VST 68

__global__ __launch_bounds__(128) void attn_b3(float* __restrict__ out)
{
    extern __shared__ float sm[];
    float* Qs  = sm;                       // 64*QST
    float* Ps  = Qs + 64 * QST;            // 64*QST
    float* Ks0 = Ps + 64 * QST;            // 2 stages * 64*QST
    float* Vs0 = Ks0 + 2 * 64 * QST;       // 2 stages * 64*VST

    const int qblk = blockIdx.x, h = blockIdx.y, b = blockIdx.z;
    const int t = threadIdx.x, w = t >> 5, lane = t & 31;
    const int g = lane >> 2, qd = lane & 3;

    const size_t base = ((size_t)(b * H_ + h)) * L_ * HD_;
    const float* Qg = g_q + base + (size_t)qblk * 64 * HD_;
    const float* Kg = g_k + base;
    const float* Vg = g_v + base;

    const int lrow = t >> 1;
    const int seg  = (t & 1) * 32;
    const unsigned ks_base = (unsigned)__cvta_generic_to_shared(Ks0 + lrow * QST + seg);
    const unsigned vs_base = (unsigned)__cvta_generic_to_shared(Vs0 + lrow * VST + seg);
    const unsigned kstage = 64 * QST * 4, vstage = 64 * VST * 4;

    // issue KV chunk 0
    {
        const float* kg = Kg + (size_t)lrow * HD_ + seg;
        const float* vg = Vg + (size_t)lrow * HD_ + seg;
#pragma unroll
        for (int i = 0; i < 8; i++) {
            CP_ASYNC16(ks_base + i * 16, kg + i * 4);
            CP_ASYNC16(vs_base + i * 16, vg + i * 4);
        }
        CP_COMMIT();
    }

    // load Q into smem
#pragma unroll
    for (int i = 0; i < 8; i++) {
        float4 v = *(const float4*)(Qg + lrow * HD_ + seg + i * 4);
        *(float4*)(Qs + lrow * QST + seg + i * 4) = v;
    }

    float mrow[2] = {-3.0e38f, -3.0e38f};
    float lrow_s[2] = {0.0f, 0.0f};
    float oacc[8][4];
#pragma unroll
    for (int ni = 0; ni < 8; ni++)
#pragma unroll
        for (int k = 0; k < 4; k++) oacc[ni][k] = 0.0f;

    const int NKB = L_ / 64;
    for (int kb = 0; kb < NKB; kb++) {
        CP_WAIT0();
        __syncthreads();
        if (kb + 1 < NKB) {
            int st = (kb + 1) & 1;
            const float* kg = Kg + (size_t)((kb + 1) * 64 + lrow) * HD_ + seg;
            const float* vg = Vg + (size_t)((kb + 1) * 64 + lrow) * HD_ + seg;
#pragma unroll
            for (int i = 0; i < 8; i++) {
                CP_ASYNC16(ks_base + st * kstage + i * 16, kg + i * 4);
                CP_ASYNC16(vs_base + st * vstage + i * 16, vg + i * 4);
            }
            CP_COMMIT();
        }
        const float* ks = Ks0 + (kb & 1) * 64 * QST;
        const float* vs = Vs0 + (kb & 1) * 64 * VST;

        // S = Q * K^T (3-term bf16), 4 chunks of 16-K
        float sacc[8][4];
#pragma unroll
        for (int ni = 0; ni < 8; ni++)
#pragma unroll
            for (int k = 0; k < 4; k++) sacc[ni][k] = 0.0f;

#pragma unroll
        for (int kk = 0; kk < 4; kk++) {
            const int k0 = kk * 16;
            unsigned qh[4], ql[4];
            const float* ap = Qs + (w * 16 + g) * QST + k0 + 2 * qd;
            float2 x0 = *(const float2*)(ap);
            float2 x1 = *(const float2*)(ap + 8 * QST);
            float2 x2 = *(const float2*)(ap + 8);
            float2 x3 = *(const float2*)(ap + 8 * QST + 8);
            split2(x0.x, x0.y, qh[0], ql[0]);
            split2(x1.x, x1.y, qh[1], ql[1]);
            split2(x2.x, x2.y, qh[2], ql[2]);
            split2(x3.x, x3.y, qh[3], ql[3]);
#pragma unroll
            for (int ni = 0; ni < 8; ni++) {
                const float* bp = ks + (ni * 8 + g) * QST + k0 + 2 * qd;
                float2 y0 = *(const float2*)(bp);
                float2 y1 = *(const float2*)(bp + 8);
                unsigned kh[2], kl[2];
                split2(y0.x, y0.y, kh[0], kl[0]);
                split2(y1.x, y1.y, kh[1], kl[1]);
                MMA_BF16(sacc[ni], qh, kh);
                MMA_BF16(sacc[ni], ql, kh);
                MMA_BF16(sacc[ni], qh, kl);
            }
        }

        // online softmax (rows: w*16 + g + 8*rr)
#pragma unroll
        for (int rr = 0; rr < 2; rr++) {
            float tm = -3.0e38f;
#pragma unroll
            for (int ni = 0; ni < 8; ni++)
                tm = fmaxf(tm, fmaxf(sacc[ni][2 * rr], sacc[ni][2 * rr + 1]));
            tm = fmaxf(tm, __shfl_xor_sync(0xffffffffu, tm, 1));
            tm = fmaxf(tm, __shfl_xor_sync(0xffffffffu, tm, 2));
            float nm = fmaxf(mrow[rr], tm);
            float sum = 0.0f;
#pragma unroll
            for (int ni = 0; ni < 8; ni++) {
                float p0 = __expf(sacc[ni][2 * rr] - nm);
                float p1 = __expf(sacc[ni][2 * rr + 1] - nm);
                sacc[ni][2 * rr] = p0;
                sacc[ni][2 * rr + 1] = p1;
                sum += p0 + p1;
            }
            sum += __shfl_xor_sync(0xffffffffu, sum, 1);
            sum += __shfl_xor_sync(0xffffffffu, sum, 2);
            float f = __expf(mrow[rr] - nm);
            lrow_s[rr] = lrow_s[rr] * f + sum;
            mrow[rr] = nm;
#pragma unroll
            for (int ni = 0; ni < 8; ni++) {
                oacc[ni][2 * rr] *= f;
                oacc[ni][2 * rr + 1] *= f;
            }
        }

        // stage P to smem (fp32)
#pragma unroll
        for (int ni = 0; ni < 8; ni++) {
            float* pp = Ps + (w * 16 + g) * QST + ni * 8 + 2 * qd;
            *(float2*)pp = make_float2(sacc[ni][0], sacc[ni][1]);
            *(float2*)(pp + 8 * QST) = make_float2(sacc[ni][2], sacc[ni][3]);
        }
        __syncthreads();

        // O += P * V (3-term bf16), 4 chunks of 16-K over kv
#pragma unroll
        for (int kk = 0; kk < 4; kk++) {
            const int k0 = kk * 16;
            unsigned ph[4], pl[4];
            const float* ap = Ps + (w * 16 + g) * QST + k0 + 2 * qd;
            float2 x0 = *(const float2*)(ap);
            float2 x1 = *(const float2*)(ap + 8 * QST);
            float2 x2 = *(const float2*)(ap + 8);
            float2 x3 = *(const float2*)(ap + 8 * QST + 8);
            split2(x0.x, x0.y, ph[0], pl[0]);
            split2(x1.x, x1.y, ph[1], pl[1]);
            split2(x2.x, x2.y, ph[2], pl[2]);
            split2(x3.x, x3.y, ph[3], pl[3]);
#pragma unroll
            for (int ni = 0; ni < 8; ni++) {
                const float* bp = vs + (k0 + 2 * qd) * VST + ni * 8 + g;
                float v00 = bp[0];
                float v01 = bp[VST];
                float v10 = bp[8 * VST];
                float v11 = bp[9 * VST];
                unsigned vh[2], vl[2];
                split2(v00, v01, vh[0], vl[0]);
                split2(v10, v11, vh[1], vl[1]);
                MMA_BF16(oacc[ni], ph, vh);
                MMA_BF16(oacc[ni], pl, vh);
                MMA_BF16(oacc[ni], ph, vl);
            }
        }
    }

    // epilogue: normalize and write [b,l,d]
#pragma unroll
    for (int rr = 0; rr < 2; rr++) {
        int row = qblk * 64 + w * 16 + g + rr * 8;
        float inv = 1.0f / lrow_s[rr];
        float* op = out + (size_t)(b * L_ + row) * D_ + h * HD_ + 2 * qd;
#pragma unroll
        for (int ni = 0; ni < 8; ni++) {
            float2 v = make_float2(oacc[ni][2 * rr] * inv, oacc[ni][2 * rr + 1] * inv);
            *(float2*)(op + ni * 8) = v;
        }
    }
}

// ---------------------------------------------------------------------------
// Launcher
// ---------------------------------------------------------------------------
extern "C" void kernel_launch(void* const* d_in, const int* in_sizes, int n_in,
                              void* d_out, int out_size)
{
    const float* x     = (const float*)d_in[0];
    const float* Wqkv  = (const float*)d_in[1];
    const float* Wproj = (const float*)d_in[2];
    float* out = (float*)d_out;

    float *qkv_p, *attn_p;
    cudaGetSymbolAddress((void**)&qkv_p, g_qkv);
    cudaGetSymbolAddress((void**)&attn_p, g_attn);

    const int smem_gemm = 4 * 128 * GST * sizeof(float);                               // 81920
    const int smem_attn = (4 * 64 * QST + 2 * 64 * VST) * sizeof(float);               // 108544
    cudaFuncSetAttribute(gemm_b3, cudaFuncAttributeMaxDynamicSharedMemorySize, smem_gemm);
    cudaFuncSetAttribute(attn_b3, cudaFuncAttributeMaxDynamicSharedMemorySize, smem_attn);

    // 1) QKV projection
    gemm_b3<<<dim3(QKV_N / 128, M_ / 128), 256, smem_gemm>>>(x, Wqkv, qkv_p, M_, QKV_N, D_);

    // 2) RoPE + split
    rope_split<<<(B_ * H_ * L_ * 32) / 256, 256>>>(qkv_p);

    // 3) Attention
    attn_b3<<<dim3(L_ / 64, H_, B_), 128, smem_attn>>>(attn_p);

    // 4) Output projection
    gemm_b3<<<dim3(D_ / 128, M_ / 128), 256, smem_gemm>>>(attn_p, Wproj, out, M_, D_, D_);
}

// round 5
// speedup vs baseline: 2.4258x; 1.2889x over previous
#include <cuda_runtime.h>
#include <cuda_bf16.h>
#include <math.h>

// Problem constants
#define B_  4
#define L_  2048
#define D_  1024
#define H_  16
#define HD_ 64
#define M_  (B_ * L_)          // 8192
#define QKV_N (3 * D_)         // 3072

typedef __nv_bfloat16 bf16;

// ---------------------------------------------------------------------------
// Scratch (device globals)
// ---------------------------------------------------------------------------
__device__ float g_qkv[M_ * QKV_N];                    // fp32 qkv rows
__device__ bf16 g_xh[M_ * D_],     g_xl[M_ * D_];      // x hi/lo
__device__ bf16 g_wqh[QKV_N * D_], g_wql[QKV_N * D_];  // W_qkv hi/lo
__device__ bf16 g_wph[D_ * D_],    g_wpl[D_ * D_];     // W_proj hi/lo
__device__ bf16 g_qh[M_ * D_], g_ql[M_ * D_];          // Q [b,h,l,hd] hi/lo
__device__ bf16 g_kh[M_ * D_], g_kl[M_ * D_];          // K
__device__ bf16 g_vh[M_ * D_], g_vl[M_ * D_];          // V
__device__ bf16 g_aoh[M_ * D_], g_aol[M_ * D_];        // attn out [b,l,d] hi/lo

// ---------------------------------------------------------------------------
// Helpers
// ---------------------------------------------------------------------------
// Split pair of fp32 into packed bf16 hi/lo (element0 in low 16 bits).
__device__ __forceinline__ void split2(float x0, float x1,
                                       unsigned& hi, unsigned& lo) {
    unsigned h;
    asm("cvt.rn.bf16x2.f32 %0, %1, %2;" : "=r"(h) : "f"(x1), "f"(x0));
    float h0 = __uint_as_float(h << 16);
    float h1 = __uint_as_float(h & 0xffff0000u);
    float r0 = x0 - h0;
    float r1 = x1 - h1;
    unsigned l;
    asm("cvt.rn.bf16x2.f32 %0, %1, %2;" : "=r"(l) : "f"(r1), "f"(r0));
    hi = h; lo = l;
}

#define MMA_BF16(d, a, b)                                                     \
    asm volatile(                                                             \
        "mma.sync.aligned.m16n8k16.row.col.f32.bf16.bf16.f32 "                \
        "{%0,%1,%2,%3}, {%4,%5,%6,%7}, {%8,%9}, {%0,%1,%2,%3};"               \
        : "+f"((d)[0]), "+f"((d)[1]), "+f"((d)[2]), "+f"((d)[3])              \
        : "r"((a)[0]), "r"((a)[1]), "r"((a)[2]), "r"((a)[3]),                 \
          "r"((b)[0]), "r"((b)[1]))

#define CP_ASYNC16(smem_u32, gptr)                                            \
    asm volatile("cp.async.cg.shared.global [%0], [%1], 16;"                  \
                 :: "r"(smem_u32), "l"(gptr))
#define CP_COMMIT()  asm volatile("cp.async.commit_group;" ::: "memory")
#define CP_WAIT0()   asm volatile("cp.async.wait_group 0;" ::: "memory")

__device__ __forceinline__ void ldsm4(unsigned& r0, unsigned& r1,
                                      unsigned& r2, unsigned& r3, unsigned a) {
    asm volatile("ldmatrix.sync.aligned.m8n8.x4.shared.b16 {%0,%1,%2,%3}, [%4];"
                 : "=r"(r0), "=r"(r1), "=r"(r2), "=r"(r3) : "r"(a));
}
__device__ __forceinline__ void ldsm4t(unsigned& r0, unsigned& r1,
                                       unsigned& r2, unsigned& r3, unsigned a) {
    asm volatile("ldmatrix.sync.aligned.m8n8.x4.trans.shared.b16 {%0,%1,%2,%3}, [%4];"
                 : "=r"(r0), "=r"(r1), "=r"(r2), "=r"(r3) : "r"(a));
}

// ---------------------------------------------------------------------------
// fp32 -> bf16 hi/lo split conversion (float4 per thread)
// ---------------------------------------------------------------------------
__global__ __launch_bounds__(256) void conv_split(
    const float* __restrict__ in, bf16* __restrict__ hi, bf16* __restrict__ lo)
{
    int i = blockIdx.x * blockDim.x + threadIdx.x;
    float4 v = ((const float4*)in)[i];
    unsigned h0, l0, h1, l1;
    split2(v.x, v.y, h0, l0);
    split2(v.z, v.w, h1, l1);
    ((uint2*)hi)[i] = make_uint2(h0, h1);
    ((uint2*)lo)[i] = make_uint2(l0, l1);
}

// ---------------------------------------------------------------------------
// 3-term bf16 NT GEMM, pre-split inputs: C[M,N] = (Ah+Al)[M,K]*(Wh+Wl)[N,K]^T
// CTA 128x128x32, 256 threads (8 warps: 2m x 4n), warp tile 64x32.
// bf16 smem tiles, row stride 40 els (80B == odd*16 mod 128): LDSM-conflict-free.
// ---------------------------------------------------------------------------
#define SB  40
#define STG (128 * SB)       // elements per stage-tile

__global__ __launch_bounds__(256, 2) void gemm_b3(
    const bf16* __restrict__ Ah, const bf16* __restrict__ Al,
    const bf16* __restrict__ Wh, const bf16* __restrict__ Wl,
    float* __restrict__ C, int M, int N, int K)
{
    extern __shared__ __align__(16) bf16 sm[];
    // element offsets: [AH s0,s1][AL s0,s1][WH s0,s1][WL s0,s1]
    const unsigned AHo = 0, ALo = 2 * STG, WHo = 4 * STG, WLo = 6 * STG;

    const int t = threadIdx.x;
    const int w = t >> 5, lane = t & 31;
    const int g = lane >> 2, qd = lane & 3;
    const int wm = (w & 1) * 64, wn = (w >> 1) * 32;
    const int bm = blockIdx.y * 128, bn = blockIdx.x * 128;

    const int laneRow = lane & 7, qR = (lane >> 3) & 1, qK = (lane >> 4) & 1;

    // staging: thread -> (row, half)
    const int srow = t >> 1, shalf = t & 1;
    const size_t gaoff = (size_t)(bm + srow) * K + shalf * 16;
    const size_t gwoff = (size_t)(bn + srow) * K + shalf * 16;
    const unsigned smem0 = (unsigned)__cvta_generic_to_shared(sm);
    const unsigned stoff = (srow * SB + shalf * 16) * 2;
    const unsigned stageB = STG * 2;

    float acc[4][4][4];
#pragma unroll
    for (int mi = 0; mi < 4; mi++)
#pragma unroll
        for (int ni = 0; ni < 4; ni++)
#pragma unroll
            for (int k = 0; k < 4; k++) acc[mi][ni][k] = 0.0f;

#pragma unroll
    for (int j = 0; j < 2; j++) {
        CP_ASYNC16(smem0 + AHo * 2 + stoff + j * 16, Ah + gaoff + j * 8);
        CP_ASYNC16(smem0 + ALo * 2 + stoff + j * 16, Al + gaoff + j * 8);
        CP_ASYNC16(smem0 + WHo * 2 + stoff + j * 16, Wh + gwoff + j * 8);
        CP_ASYNC16(smem0 + WLo * 2 + stoff + j * 16, Wl + gwoff + j * 8);
    }
    CP_COMMIT();

    const int NK = K >> 5;
    for (int ks = 0; ks < NK; ks++) {
        CP_WAIT0();
        __syncthreads();
        if (ks + 1 < NK) {
            unsigned sB = ((ks + 1) & 1) * stageB;
            int k0 = (ks + 1) * 32;
#pragma unroll
            for (int j = 0; j < 2; j++) {
                CP_ASYNC16(smem0 + AHo * 2 + sB + stoff + j * 16, Ah + gaoff + k0 + j * 8);
                CP_ASYNC16(smem0 + ALo * 2 + sB + stoff + j * 16, Al + gaoff + k0 + j * 8);
                CP_ASYNC16(smem0 + WHo * 2 + sB + stoff + j * 16, Wh + gwoff + k0 + j * 8);
                CP_ASYNC16(smem0 + WLo * 2 + sB + stoff + j * 16, Wl + gwoff + k0 + j * 8);
            }
            CP_COMMIT();
        }
        const unsigned sB = (ks & 1) * stageB;

#pragma unroll
        for (int kc = 0; kc < 2; kc++) {
            unsigned ahf[4][4], alf[4][4];
#pragma unroll
            for (int mi = 0; mi < 4; mi++) {
                unsigned ra = ((wm + mi * 16 + laneRow + qR * 8) * SB + kc * 16 + qK * 8) * 2;
                ldsm4(ahf[mi][0], ahf[mi][1], ahf[mi][2], ahf[mi][3],
                      smem0 + AHo * 2 + sB + ra);
                ldsm4(alf[mi][0], alf[mi][1], alf[mi][2], alf[mi][3],
                      smem0 + ALo * 2 + sB + ra);
            }
#pragma unroll
            for (int p = 0; p < 2; p++) {
                unsigned rb = ((wn + p * 16 + laneRow + qK * 8) * SB + kc * 16 + qR * 8) * 2;
                unsigned bh[4], bl[4];
                ldsm4(bh[0], bh[1], bh[2], bh[3], smem0 + WHo * 2 + sB + rb);
                ldsm4(bl[0], bl[1], bl[2], bl[3], smem0 + WLo * 2 + sB + rb);
                unsigned bh0[2] = {bh[0], bh[1]}, bh1[2] = {bh[2], bh[3]};
                unsigned bl0[2] = {bl[0], bl[1]}, bl1[2] = {bl[2], bl[3]};
#pragma unroll
                for (int mi = 0; mi < 4; mi++) {
                    MMA_BF16(acc[mi][2 * p],     ahf[mi], bh0);
                    MMA_BF16(acc[mi][2 * p],     alf[mi], bh0);
                    MMA_BF16(acc[mi][2 * p],     ahf[mi], bl0);
                    MMA_BF16(acc[mi][2 * p + 1], ahf[mi], bh1);
                    MMA_BF16(acc[mi][2 * p + 1], alf[mi], bh1);
                    MMA_BF16(acc[mi][2 * p + 1], ahf[mi], bl1);
                }
            }
        }
    }

    // epilogue (fp32)
#pragma unroll
    for (int mi = 0; mi < 4; mi++)
#pragma unroll
        for (int rr = 0; rr < 2; rr++) {
            int row = bm + wm + mi * 16 + g + rr * 8;
            float* Cp = C + (size_t)row * N + bn + wn + 2 * qd;
#pragma unroll
            for (int ni = 0; ni < 4; ni++) {
                *(float2*)(Cp + ni * 8) =
                    make_float2(acc[mi][ni][2 * rr], acc[mi][ni][2 * rr + 1]);
            }
        }
}

// ---------------------------------------------------------------------------
// RoPE + split to [b,h,l,hd]; Q pre-scaled; writes bf16 hi/lo directly.
// ---------------------------------------------------------------------------
__global__ __launch_bounds__(256) void rope_split(const float* __restrict__ qkv)
{
    int idx = blockIdx.x * blockDim.x + threadIdx.x;
    int i = idx & 31;
    int l = (idx >> 5) & (L_ - 1);
    int h = (idx >> 16) & (H_ - 1);
    int b = idx >> 20;

    const float* row = qkv + (size_t)(b * L_ + l) * QKV_N;

    float inv = powf(10000.0f, -(float)(2 * i) * (1.0f / (float)HD_));
    float ang = (float)l * inv;
    float cs = cosf(ang);
    float sn = sinf(ang);

    int off = h * HD_ + 2 * i;
    float q1 = row[off],      q2 = row[off + 1];
    float k1 = row[D_ + off], k2 = row[D_ + off + 1];

    size_t o = ((size_t)((b * H_ + h) * L_ + l)) * HD_;
    const float qscale = 0.125f;
    float qa = (q1 * cs - q2 * sn) * qscale;
    float qb = (q1 * sn + q2 * cs) * qscale;
    float ka = k1 * cs - k2 * sn;
    float kb = k1 * sn + k2 * cs;
    float va = row[2 * D_ + h * HD_ + i];
    float vb = row[2 * D_ + h * HD_ + i + 32];

    bf16 t;
    t = __float2bfloat16(qa); g_qh[o + i] = t;      g_ql[o + i]      = __float2bfloat16(qa - __bfloat162float(t));
    t = __float2bfloat16(qb); g_qh[o + i + 32] = t; g_ql[o + i + 32] = __float2bfloat16(qb - __bfloat162float(t));
    t = __float2bfloat16(ka); g_kh[o + i] = t;      g_kl[o + i]      = __float2bfloat16(ka - __bfloat162float(t));
    t = __float2bfloat16(kb); g_kh[o + i + 32] = t; g_kl[o + i + 32] = __float2bfloat16(kb - __bfloat162float(t));
    t = __float2bfloat16(va); g_vh[o + i] = t;      g_vl[o + i]      = __float2bfloat16(va - __bfloat162float(t));
    t = __float2bfloat16(vb); g_vh[o + i + 32] = t; g_vl[o + i + 32] = __float2bfloat16(vb - __bfloat162float(t));
}

// ---------------------------------------------------------------------------
// Flash attention, 3-term bf16, pre-split inputs, register-repacked P.
// CTA = 64 queries, 4 warps x 16 rows. K/V 64-chunks double buffered.
// Smem row stride 72 els (144B == odd*16 mod 128): LDSM-conflict-free.
// Output written as bf16 hi/lo for the proj gemm.
// ---------------------------------------------------------------------------
#define SA 72
#define ATILE (64 * SA)

__global__ __launch_bounds__(128) void attn_b3()
{
    extern __shared__ __align__(16) bf16 sma[];
    // element offsets
    const unsigned QHo = 0, QLo = ATILE;
    const unsigned KHo = 2 * ATILE, KLo = 4 * ATILE;
    const unsigned VHo = 6 * ATILE, VLo = 8 * ATILE;   // + s*ATILE each

    const int qblk = blockIdx.x, h = blockIdx.y, b = blockIdx.z;
    const int t = threadIdx.x, w = t >> 5, lane = t & 31;
    const int g = lane >> 2, qd = lane & 3;
    const int laneRow = lane & 7, qR = (lane >> 3) & 1, qK = (lane >> 4) & 1;

    const size_t base = ((size_t)(b * H_ + h)) * L_ * HD_;
    const bf16* Qh = g_qh + base + (size_t)qblk * 64 * HD_;
    const bf16* Ql = g_ql + base + (size_t)qblk * 64 * HD_;
    const bf16* Kh = g_kh + base;
    const bf16* Kl = g_kl + base;
    const bf16* Vh = g_vh + base;
    const bf16* Vl = g_vl + base;

    const unsigned smem0 = (unsigned)__cvta_generic_to_shared(sma);
    const int srow = t >> 1, shalf = t & 1;
    const unsigned stoff = (srow * SA) * 2 + shalf * 64;   // byte offset within tile
    const size_t goff = (size_t)srow * HD_ + shalf * 32;   // element offset

    // stage 0: Q + KV chunk 0
#pragma unroll
    for (int j = 0; j < 4; j++) {
        CP_ASYNC16(smem0 + QHo * 2 + stoff + j * 16, Qh + goff + j * 8);
        CP_ASYNC16(smem0 + QLo * 2 + stoff + j * 16, Ql + goff + j * 8);
        CP_ASYNC16(smem0 + KHo * 2 + stoff + j * 16, Kh + goff + j * 8);
        CP_ASYNC16(smem0 + KLo * 2 + stoff + j * 16, Kl + goff + j * 8);
        CP_ASYNC16(smem0 + VHo * 2 + stoff + j * 16, Vh + goff + j * 8);
        CP_ASYNC16(smem0 + VLo * 2 + stoff + j * 16, Vl + goff + j * 8);
    }
    CP_COMMIT();

    float mrow[2] = {-3.0e38f, -3.0e38f};
    float lsum[2] = {0.0f, 0.0f};
    float oacc[8][4];
#pragma unroll
    for (int ni = 0; ni < 8; ni++)
#pragma unroll
        for (int k = 0; k < 4; k++) oacc[ni][k] = 0.0f;

    const int NKB = L_ / 64;
    for (int kb = 0; kb < NKB; kb++) {
        CP_WAIT0();
        __syncthreads();
        if (kb + 1 < NKB) {
            unsigned sB = ((kb + 1) & 1) * ATILE * 2;
            size_t go = (size_t)((kb + 1) * 64) * HD_ + goff;
#pragma unroll
            for (int j = 0; j < 4; j++) {
                CP_ASYNC16(smem0 + KHo * 2 + sB + stoff + j * 16, Kh + go + j * 8);
                CP_ASYNC16(smem0 + KLo * 2 + sB + stoff + j * 16, Kl + go + j * 8);
                CP_ASYNC16(smem0 + VHo * 2 + sB + stoff + j * 16, Vh + go + j * 8);
                CP_ASYNC16(smem0 + VLo * 2 + sB + stoff + j * 16, Vl + go + j * 8);
            }
            CP_COMMIT();
        }
        const unsigned sB = (kb & 1) * ATILE * 2;

        // ---- S = Q*K^T (3-term) ----
        float sacc[8][4];
#pragma unroll
        for (int ni = 0; ni < 8; ni++)
#pragma unroll
            for (int k = 0; k < 4; k++) sacc[ni][k] = 0.0f;

#pragma unroll
        for (int kc = 0; kc < 4; kc++) {
            unsigned qh[4], ql[4];
            unsigned rq = ((w * 16 + laneRow + qR * 8) * SA + kc * 16 + qK * 8) * 2;
            ldsm4(qh[0], qh[1], qh[2], qh[3], smem0 + QHo * 2 + rq);
            ldsm4(ql[0], ql[1], ql[2], ql[3], smem0 + QLo * 2 + rq);
#pragma unroll
            for (int p = 0; p < 4; p++) {
                unsigned rk = ((p * 16 + laneRow + qK * 8) * SA + kc * 16 + qR * 8) * 2;
                unsigned kh[4], kl[4];
                ldsm4(kh[0], kh[1], kh[2], kh[3], smem0 + KHo * 2 + sB + rk);
                ldsm4(kl[0], kl[1], kl[2], kl[3], smem0 + KLo * 2 + sB + rk);
                unsigned kh0[2] = {kh[0], kh[1]}, kh1[2] = {kh[2], kh[3]};
                unsigned kl0[2] = {kl[0], kl[1]}, kl1[2] = {kl[2], kl[3]};
                MMA_BF16(sacc[2 * p],     qh, kh0);
                MMA_BF16(sacc[2 * p],     ql, kh0);
                MMA_BF16(sacc[2 * p],     qh, kl0);
                MMA_BF16(sacc[2 * p + 1], qh, kh1);
                MMA_BF16(sacc[2 * p + 1], ql, kh1);
                MMA_BF16(sacc[2 * p + 1], qh, kl1);
            }
        }

        // ---- online softmax ----
#pragma unroll
        for (int rr = 0; rr < 2; rr++) {
            float tm = -3.0e38f;
#pragma unroll
            for (int ni = 0; ni < 8; ni++)
                tm = fmaxf(tm, fmaxf(sacc[ni][2 * rr], sacc[ni][2 * rr + 1]));
            tm = fmaxf(tm, __shfl_xor_sync(0xffffffffu, tm, 1));
            tm = fmaxf(tm, __shfl_xor_sync(0xffffffffu, tm, 2));
            float nm = fmaxf(mrow[rr], tm);
            float sum = 0.0f;
#pragma unroll
            for (int ni = 0; ni < 8; ni++) {
                float p0 = __expf(sacc[ni][2 * rr] - nm);
                float p1 = __expf(sacc[ni][2 * rr + 1] - nm);
                sacc[ni][2 * rr] = p0;
                sacc[ni][2 * rr + 1] = p1;
                sum += p0 + p1;
            }
            sum += __shfl_xor_sync(0xffffffffu, sum, 1);
            sum += __shfl_xor_sync(0xffffffffu, sum, 2);
            float f = __expf(mrow[rr] - nm);
            lsum[rr] = lsum[rr] * f + sum;
            mrow[rr] = nm;
#pragma unroll
            for (int ni = 0; ni < 8; ni++) {
                oacc[ni][2 * rr] *= f;
                oacc[ni][2 * rr + 1] *= f;
            }
        }

        // ---- O += P*V (P repacked from sacc registers, 3-term) ----
#pragma unroll
        for (int kc = 0; kc < 4; kc++) {
            unsigned ph[4], pl[4];
            split2(sacc[2 * kc][0],     sacc[2 * kc][1],     ph[0], pl[0]);
            split2(sacc[2 * kc][2],     sacc[2 * kc][3],     ph[1], pl[1]);
            split2(sacc[2 * kc + 1][0], sacc[2 * kc + 1][1], ph[2], pl[2]);
            split2(sacc[2 * kc + 1][2], sacc[2 * kc + 1][3], ph[3], pl[3]);
#pragma unroll
            for (int p = 0; p < 4; p++) {
                unsigned rv = ((kc * 16 + laneRow + qR * 8) * SA + p * 16 + qK * 8) * 2;
                unsigned vh[4], vl[4];
                ldsm4t(vh[0], vh[1], vh[2], vh[3], smem0 + VHo * 2 + sB + rv);
                ldsm4t(vl[0], vl[1], vl[2], vl[3], smem0 + VLo * 2 + sB + rv);
                unsigned vh0[2] = {vh[0], vh[1]}, vh1[2] = {vh[2], vh[3]};
                unsigned vl0[2] = {vl[0], vl[1]}, vl1[2] = {vl[2], vl[3]};
                MMA_BF16(oacc[2 * p],     ph, vh0);
                MMA_BF16(oacc[2 * p],     pl, vh0);
                MMA_BF16(oacc[2 * p],     ph, vl0);
                MMA_BF16(oacc[2 * p + 1], ph, vh1);
                MMA_BF16(oacc[2 * p + 1], pl, vh1);
                MMA_BF16(oacc[2 * p + 1], ph, vl1);
            }
        }
    }

    // epilogue: normalize, split to bf16 hi/lo, write [b,l,d]
#pragma unroll
    for (int rr = 0; rr < 2; rr++) {
        int row = qblk * 64 + w * 16 + g + rr * 8;
        float inv = 1.0f / lsum[rr];
        unsigned* oh = (unsigned*)(g_aoh + (size_t)(b * L_ + row) * D_ + h * HD_);
        unsigned* ol = (unsigned*)(g_aol + (size_t)(b * L_ + row) * D_ + h * HD_);
#pragma unroll
        for (int ni = 0; ni < 8; ni++) {
            unsigned hv, lv;
            split2(oacc[ni][2 * rr] * inv, oacc[ni][2 * rr + 1] * inv, hv, lv);
            oh[ni * 4 + qd] = hv;
            ol[ni * 4 + qd] = lv;
        }
    }
}

// ---------------------------------------------------------------------------
// Launcher
// ---------------------------------------------------------------------------
extern "C" void kernel_launch(void* const* d_in, const int* in_sizes, int n_in,
                              void* d_out, int out_size)
{
    const float* x     = (const float*)d_in[0];
    const float* Wqkv  = (const float*)d_in[1];
    const float* Wproj = (const float*)d_in[2];
    float* out = (float*)d_out;

    float* qkv_p;
    bf16 *xh, *xl, *wqh, *wql, *wph, *wpl, *aoh, *aol;
    cudaGetSymbolAddress((void**)&qkv_p, g_qkv);
    cudaGetSymbolAddress((void**)&xh,  g_xh);  cudaGetSymbolAddress((void**)&xl,  g_xl);
    cudaGetSymbolAddress((void**)&wqh, g_wqh); cudaGetSymbolAddress((void**)&wql, g_wql);
    cudaGetSymbolAddress((void**)&wph, g_wph); cudaGetSymbolAddress((void**)&wpl, g_wpl);
    cudaGetSymbolAddress((void**)&aoh, g_aoh); cudaGetSymbolAddress((void**)&aol, g_aol);

    const int smem_gemm = 8 * STG * sizeof(bf16);        // 81920
    const int smem_attn = 10 * ATILE * sizeof(bf16);     // 92160
    cudaFuncSetAttribute(gemm_b3, cudaFuncAttributeMaxDynamicSharedMemorySize, smem_gemm);
    cudaFuncSetAttribute(attn_b3, cudaFuncAttributeMaxDynamicSharedMemorySize, smem_attn);

    // 0) pre-split inputs to bf16 hi/lo
    conv_split<<<(M_ * D_ / 4) / 256, 256>>>(x, xh, xl);
    conv_split<<<(QKV_N * D_ / 4) / 256, 256>>>(Wqkv, wqh, wql);
    conv_split<<<(D_ * D_ / 4) / 256, 256>>>(Wproj, wph, wpl);

    // 1) QKV projection (fp32 out)
    gemm_b3<<<dim3(QKV_N / 128, M_ / 128), 256, smem_gemm>>>(
        xh, xl, wqh, wql, qkv_p, M_, QKV_N, D_);

    // 2) RoPE + split to bf16 hi/lo [b,h,l,hd]
    rope_split<<<(B_ * H_ * L_ * 32) / 256, 256>>>(qkv_p);

    // 3) Attention (writes bf16 hi/lo attn-out)
    attn_b3<<<dim3(L_ / 64, H_, B_), 128, smem_attn>>>();

    // 4) Output projection (fp32 out)
    gemm_b3<<<dim3(D_ / 128, M_ / 128), 256, smem_gemm>>>(
        aoh, aol, wph, wpl, out, M_, D_, D_);
}

// round 6
// speedup vs baseline: 3.0247x; 1.2469x over previous
#include <cuda_runtime.h>
#include <cuda_bf16.h>
#include <math.h>

// Problem constants
#define B_  4
#define L_  2048
#define D_  1024
#define H_  16
#define HD_ 64
#define M_  (B_ * L_)          // 8192
#define QKV_N (3 * D_)         // 3072

typedef __nv_bfloat16 bf16;

// ---------------------------------------------------------------------------
// Scratch (device globals)
// ---------------------------------------------------------------------------
__device__ float g_qkv[M_ * QKV_N];                    // fp32 qkv rows
__device__ bf16 g_xh[M_ * D_],     g_xl[M_ * D_];      // x hi/lo
__device__ bf16 g_wqh[QKV_N * D_], g_wql[QKV_N * D_];  // W_qkv hi/lo
__device__ bf16 g_wph[D_ * D_],    g_wpl[D_ * D_];     // W_proj hi/lo
__device__ bf16 g_qh[M_ * D_], g_ql[M_ * D_];          // Q [b,h,l,hd] hi/lo
__device__ bf16 g_kh[M_ * D_], g_kl[M_ * D_];          // K
__device__ bf16 g_vh[M_ * D_], g_vl[M_ * D_];          // V
__device__ bf16 g_aoh[M_ * D_], g_aol[M_ * D_];        // attn out [b,l,d] hi/lo

// ---------------------------------------------------------------------------
// Helpers
// ---------------------------------------------------------------------------
__device__ __forceinline__ void split2(float x0, float x1,
                                       unsigned& hi, unsigned& lo) {
    unsigned h;
    asm("cvt.rn.bf16x2.f32 %0, %1, %2;" : "=r"(h) : "f"(x1), "f"(x0));
    float h0 = __uint_as_float(h << 16);
    float h1 = __uint_as_float(h & 0xffff0000u);
    float r0 = x0 - h0;
    float r1 = x1 - h1;
    unsigned l;
    asm("cvt.rn.bf16x2.f32 %0, %1, %2;" : "=r"(l) : "f"(r1), "f"(r0));
    hi = h; lo = l;
}

#define MMA_BF16(d, a, b)                                                     \
    asm volatile(                                                             \
        "mma.sync.aligned.m16n8k16.row.col.f32.bf16.bf16.f32 "                \
        "{%0,%1,%2,%3}, {%4,%5,%6,%7}, {%8,%9}, {%0,%1,%2,%3};"               \
        : "+f"((d)[0]), "+f"((d)[1]), "+f"((d)[2]), "+f"((d)[3])              \
        : "r"((a)[0]), "r"((a)[1]), "r"((a)[2]), "r"((a)[3]),                 \
          "r"((b)[0]), "r"((b)[1]))

#define CP_ASYNC16(smem_u32, gptr)                                            \
    asm volatile("cp.async.cg.shared.global [%0], [%1], 16;"                  \
                 :: "r"(smem_u32), "l"(gptr))
#define CP_COMMIT()  asm volatile("cp.async.commit_group;" ::: "memory")
#define CP_WAIT0()   asm volatile("cp.async.wait_group 0;" ::: "memory")

__device__ __forceinline__ void ldsm4(unsigned& r0, unsigned& r1,
                                      unsigned& r2, unsigned& r3, unsigned a) {
    asm volatile("ldmatrix.sync.aligned.m8n8.x4.shared.b16 {%0,%1,%2,%3}, [%4];"
                 : "=r"(r0), "=r"(r1), "=r"(r2), "=r"(r3) : "r"(a));
}
__device__ __forceinline__ void ldsm4t(unsigned& r0, unsigned& r1,
                                       unsigned& r2, unsigned& r3, unsigned a) {
    asm volatile("ldmatrix.sync.aligned.m8n8.x4.trans.shared.b16 {%0,%1,%2,%3}, [%4];"
                 : "=r"(r0), "=r"(r1), "=r"(r2), "=r"(r3) : "r"(a));
}

// ---------------------------------------------------------------------------
// fp32 -> bf16 hi/lo split conversion (float4 per thread)
// ---------------------------------------------------------------------------
__global__ __launch_bounds__(256) void conv_split(
    const float* __restrict__ in, bf16* __restrict__ hi, bf16* __restrict__ lo)
{
    int i = blockIdx.x * blockDim.x + threadIdx.x;
    float4 v = ((const float4*)in)[i];
    unsigned h0, l0, h1, l1;
    split2(v.x, v.y, h0, l0);
    split2(v.z, v.w, h1, l1);
    ((uint2*)hi)[i] = make_uint2(h0, h1);
    ((uint2*)lo)[i] = make_uint2(l0, l1);
}

// ---------------------------------------------------------------------------
// 3-term bf16 NT GEMM, pre-split inputs (unchanged from R5 — verified fast)
// ---------------------------------------------------------------------------
#define SB  40
#define STG (128 * SB)

__global__ __launch_bounds__(256, 2) void gemm_b3(
    const bf16* __restrict__ Ah, const bf16* __restrict__ Al,
    const bf16* __restrict__ Wh, const bf16* __restrict__ Wl,
    float* __restrict__ C, int M, int N, int K)
{
    extern __shared__ __align__(16) bf16 sm[];
    const unsigned AHo = 0, ALo = 2 * STG, WHo = 4 * STG, WLo = 6 * STG;

    const int t = threadIdx.x;
    const int w = t >> 5, lane = t & 31;
    const int g = lane >> 2, qd = lane & 3;
    const int wm = (w & 1) * 64, wn = (w >> 1) * 32;
    const int bm = blockIdx.y * 128, bn = blockIdx.x * 128;

    const int laneRow = lane & 7, qR = (lane >> 3) & 1, qK = (lane >> 4) & 1;

    const int srow = t >> 1, shalf = t & 1;
    const size_t gaoff = (size_t)(bm + srow) * K + shalf * 16;
    const size_t gwoff = (size_t)(bn + srow) * K + shalf * 16;
    const unsigned smem0 = (unsigned)__cvta_generic_to_shared(sm);
    const unsigned stoff = (srow * SB + shalf * 16) * 2;
    const unsigned stageB = STG * 2;

    float acc[4][4][4];
#pragma unroll
    for (int mi = 0; mi < 4; mi++)
#pragma unroll
        for (int ni = 0; ni < 4; ni++)
#pragma unroll
            for (int k = 0; k < 4; k++) acc[mi][ni][k] = 0.0f;

#pragma unroll
    for (int j = 0; j < 2; j++) {
        CP_ASYNC16(smem0 + AHo * 2 + stoff + j * 16, Ah + gaoff + j * 8);
        CP_ASYNC16(smem0 + ALo * 2 + stoff + j * 16, Al + gaoff + j * 8);
        CP_ASYNC16(smem0 + WHo * 2 + stoff + j * 16, Wh + gwoff + j * 8);
        CP_ASYNC16(smem0 + WLo * 2 + stoff + j * 16, Wl + gwoff + j * 8);
    }
    CP_COMMIT();

    const int NK = K >> 5;
    for (int ks = 0; ks < NK; ks++) {
        CP_WAIT0();
        __syncthreads();
        if (ks + 1 < NK) {
            unsigned sB = ((ks + 1) & 1) * stageB;
            int k0 = (ks + 1) * 32;
#pragma unroll
            for (int j = 0; j < 2; j++) {
                CP_ASYNC16(smem0 + AHo * 2 + sB + stoff + j * 16, Ah + gaoff + k0 + j * 8);
                CP_ASYNC16(smem0 + ALo * 2 + sB + stoff + j * 16, Al + gaoff + k0 + j * 8);
                CP_ASYNC16(smem0 + WHo * 2 + sB + stoff + j * 16, Wh + gwoff + k0 + j * 8);
                CP_ASYNC16(smem0 + WLo * 2 + sB + stoff + j * 16, Wl + gwoff + k0 + j * 8);
            }
            CP_COMMIT();
        }
        const unsigned sB = (ks & 1) * stageB;

#pragma unroll
        for (int kc = 0; kc < 2; kc++) {
            unsigned ahf[4][4], alf[4][4];
#pragma unroll
            for (int mi = 0; mi < 4; mi++) {
                unsigned ra = ((wm + mi * 16 + laneRow + qR * 8) * SB + kc * 16 + qK * 8) * 2;
                ldsm4(ahf[mi][0], ahf[mi][1], ahf[mi][2], ahf[mi][3],
                      smem0 + AHo * 2 + sB + ra);
                ldsm4(alf[mi][0], alf[mi][1], alf[mi][2], alf[mi][3],
                      smem0 + ALo * 2 + sB + ra);
            }
#pragma unroll
            for (int p = 0; p < 2; p++) {
                unsigned rb = ((wn + p * 16 + laneRow + qK * 8) * SB + kc * 16 + qR * 8) * 2;
                unsigned bh[4], bl[4];
                ldsm4(bh[0], bh[1], bh[2], bh[3], smem0 + WHo * 2 + sB + rb);
                ldsm4(bl[0], bl[1], bl[2], bl[3], smem0 + WLo * 2 + sB + rb);
                unsigned bh0[2] = {bh[0], bh[1]}, bh1[2] = {bh[2], bh[3]};
                unsigned bl0[2] = {bl[0], bl[1]}, bl1[2] = {bl[2], bl[3]};
#pragma unroll
                for (int mi = 0; mi < 4; mi++) {
                    MMA_BF16(acc[mi][2 * p],     ahf[mi], bh0);
                    MMA_BF16(acc[mi][2 * p],     alf[mi], bh0);
                    MMA_BF16(acc[mi][2 * p],     ahf[mi], bl0);
                    MMA_BF16(acc[mi][2 * p + 1], ahf[mi], bh1);
                    MMA_BF16(acc[mi][2 * p + 1], alf[mi], bh1);
                    MMA_BF16(acc[mi][2 * p + 1], ahf[mi], bl1);
                }
            }
        }
    }

#pragma unroll
    for (int mi = 0; mi < 4; mi++)
#pragma unroll
        for (int rr = 0; rr < 2; rr++) {
            int row = bm + wm + mi * 16 + g + rr * 8;
            float* Cp = C + (size_t)row * N + bn + wn + 2 * qd;
#pragma unroll
            for (int ni = 0; ni < 4; ni++) {
                *(float2*)(Cp + ni * 8) =
                    make_float2(acc[mi][ni][2 * rr], acc[mi][ni][2 * rr + 1]);
            }
        }
}

// ---------------------------------------------------------------------------
// RoPE + split to [b,h,l,hd]; Q pre-scaled; writes bf16 hi/lo directly.
// ---------------------------------------------------------------------------
__global__ __launch_bounds__(256) void rope_split(const float* __restrict__ qkv)
{
    int idx = blockIdx.x * blockDim.x + threadIdx.x;
    int i = idx & 31;
    int l = (idx >> 5) & (L_ - 1);
    int h = (idx >> 16) & (H_ - 1);
    int b = idx >> 20;

    const float* row = qkv + (size_t)(b * L_ + l) * QKV_N;

    float inv = powf(10000.0f, -(float)(2 * i) * (1.0f / (float)HD_));
    float ang = (float)l * inv;
    float cs = cosf(ang);
    float sn = sinf(ang);

    int off = h * HD_ + 2 * i;
    float q1 = row[off],      q2 = row[off + 1];
    float k1 = row[D_ + off], k2 = row[D_ + off + 1];

    size_t o = ((size_t)((b * H_ + h) * L_ + l)) * HD_;
    const float qscale = 0.125f;
    float qa = (q1 * cs - q2 * sn) * qscale;
    float qb = (q1 * sn + q2 * cs) * qscale;
    float ka = k1 * cs - k2 * sn;
    float kb = k1 * sn + k2 * cs;
    float va = row[2 * D_ + h * HD_ + i];
    float vb = row[2 * D_ + h * HD_ + i + 32];

    bf16 t;
    t = __float2bfloat16(qa); g_qh[o + i] = t;      g_ql[o + i]      = __float2bfloat16(qa - __bfloat162float(t));
    t = __float2bfloat16(qb); g_qh[o + i + 32] = t; g_ql[o + i + 32] = __float2bfloat16(qb - __bfloat162float(t));
    t = __float2bfloat16(ka); g_kh[o + i] = t;      g_kl[o + i]      = __float2bfloat16(ka - __bfloat162float(t));
    t = __float2bfloat16(kb); g_kh[o + i + 32] = t; g_kl[o + i + 32] = __float2bfloat16(kb - __bfloat162float(t));
    t = __float2bfloat16(va); g_vh[o + i] = t;      g_vl[o + i]      = __float2bfloat16(va - __bfloat162float(t));
    t = __float2bfloat16(vb); g_vh[o + i + 32] = t; g_vl[o + i + 32] = __float2bfloat16(vb - __bfloat162float(t));
}

// ---------------------------------------------------------------------------
// Flash attention, 3-term bf16. CTA = 128 queries, 8 warps x 16 q-rows,
// 256 threads. K/V 64-chunks double-buffered. Row stride 72 els.
// ---------------------------------------------------------------------------
#define SA 72
#define QTILE (128 * SA)
#define KTILE (64 * SA)

__global__ __launch_bounds__(256, 2) void attn_b3()
{
    extern __shared__ __align__(16) bf16 sma[];
    // element offsets
    const unsigned QHo = 0, QLo = QTILE;
    const unsigned KHo = 2 * QTILE;                 // + s*KTILE
    const unsigned KLo = 2 * QTILE + 2 * KTILE;
    const unsigned VHo = 2 * QTILE + 4 * KTILE;
    const unsigned VLo = 2 * QTILE + 6 * KTILE;

    const int qblk = blockIdx.x, h = blockIdx.y, b = blockIdx.z;
    const int t = threadIdx.x, w = t >> 5, lane = t & 31;
    const int g = lane >> 2, qd = lane & 3;
    const int laneRow = lane & 7, qR = (lane >> 3) & 1, qK = (lane >> 4) & 1;

    const size_t base = ((size_t)(b * H_ + h)) * L_ * HD_;
    const bf16* Qh = g_qh + base + (size_t)qblk * 128 * HD_;
    const bf16* Ql = g_ql + base + (size_t)qblk * 128 * HD_;
    const bf16* Kh = g_kh + base;
    const bf16* Kl = g_kl + base;
    const bf16* Vh = g_vh + base;
    const bf16* Vl = g_vl + base;

    const unsigned smem0 = (unsigned)__cvta_generic_to_shared(sma);

    // Q staging: 256 threads, 128 rows, half-row (32 els = 4x16B) each
    const int qrow = t >> 1, qhalf = t & 1;
    const unsigned qoffB = (qrow * SA) * 2 + qhalf * 64;
    const size_t qgoff = (size_t)qrow * HD_ + qhalf * 32;
    // K/V staging: 64 rows, quarter-row (16 els = 2x16B) each
    const int krow = t >> 2, kq = t & 3;
    const unsigned koffB = (krow * SA) * 2 + kq * 32;
    const size_t kgoff = (size_t)krow * HD_ + kq * 16;

    // stage 0: Q + KV chunk 0
#pragma unroll
    for (int j = 0; j < 4; j++) {
        CP_ASYNC16(smem0 + QHo * 2 + qoffB + j * 16, Qh + qgoff + j * 8);
        CP_ASYNC16(smem0 + QLo * 2 + qoffB + j * 16, Ql + qgoff + j * 8);
    }
#pragma unroll
    for (int j = 0; j < 2; j++) {
        CP_ASYNC16(smem0 + KHo * 2 + koffB + j * 16, Kh + kgoff + j * 8);
        CP_ASYNC16(smem0 + KLo * 2 + koffB + j * 16, Kl + kgoff + j * 8);
        CP_ASYNC16(smem0 + VHo * 2 + koffB + j * 16, Vh + kgoff + j * 8);
        CP_ASYNC16(smem0 + VLo * 2 + koffB + j * 16, Vl + kgoff + j * 8);
    }
    CP_COMMIT();

    float mrow[2] = {-3.0e38f, -3.0e38f};
    float lsum[2] = {0.0f, 0.0f};
    float oacc[8][4];
#pragma unroll
    for (int ni = 0; ni < 8; ni++)
#pragma unroll
        for (int k = 0; k < 4; k++) oacc[ni][k] = 0.0f;

    const int NKB = L_ / 64;
    for (int kb = 0; kb < NKB; kb++) {
        CP_WAIT0();
        __syncthreads();
        if (kb + 1 < NKB) {
            unsigned sB = ((kb + 1) & 1) * KTILE * 2;
            size_t go = (size_t)((kb + 1) * 64) * HD_ + kgoff;
#pragma unroll
            for (int j = 0; j < 2; j++) {
                CP_ASYNC16(smem0 + KHo * 2 + sB + koffB + j * 16, Kh + go + j * 8);
                CP_ASYNC16(smem0 + KLo * 2 + sB + koffB + j * 16, Kl + go + j * 8);
                CP_ASYNC16(smem0 + VHo * 2 + sB + koffB + j * 16, Vh + go + j * 8);
                CP_ASYNC16(smem0 + VLo * 2 + sB + koffB + j * 16, Vl + go + j * 8);
            }
            CP_COMMIT();
        }
        const unsigned sB = (kb & 1) * KTILE * 2;

        // ---- S = Q*K^T (3-term) ----
        float sacc[8][4];
#pragma unroll
        for (int ni = 0; ni < 8; ni++)
#pragma unroll
            for (int k = 0; k < 4; k++) sacc[ni][k] = 0.0f;

#pragma unroll
        for (int kc = 0; kc < 4; kc++) {
            unsigned qhf[4], qlf[4];
            unsigned rq = ((w * 16 + laneRow + qR * 8) * SA + kc * 16 + qK * 8) * 2;
            ldsm4(qhf[0], qhf[1], qhf[2], qhf[3], smem0 + QHo * 2 + rq);
            ldsm4(qlf[0], qlf[1], qlf[2], qlf[3], smem0 + QLo * 2 + rq);
#pragma unroll
            for (int p = 0; p < 4; p++) {
                unsigned rk = ((p * 16 + laneRow + qK * 8) * SA + kc * 16 + qR * 8) * 2;
                unsigned kh[4], kl[4];
                ldsm4(kh[0], kh[1], kh[2], kh[3], smem0 + KHo * 2 + sB + rk);
                ldsm4(kl[0], kl[1], kl[2], kl[3], smem0 + KLo * 2 + sB + rk);
                unsigned kh0[2] = {kh[0], kh[1]}, kh1[2] = {kh[2], kh[3]};
                unsigned kl0[2] = {kl[0], kl[1]}, kl1[2] = {kl[2], kl[3]};
                MMA_BF16(sacc[2 * p],     qhf, kh0);
                MMA_BF16(sacc[2 * p],     qlf, kh0);
                MMA_BF16(sacc[2 * p],     qhf, kl0);
                MMA_BF16(sacc[2 * p + 1], qhf, kh1);
                MMA_BF16(sacc[2 * p + 1], qlf, kh1);
                MMA_BF16(sacc[2 * p + 1], qhf, kl1);
            }
        }

        // ---- online softmax ----
#pragma unroll
        for (int rr = 0; rr < 2; rr++) {
            float tm = -3.0e38f;
#pragma unroll
            for (int ni = 0; ni < 8; ni++)
                tm = fmaxf(tm, fmaxf(sacc[ni][2 * rr], sacc[ni][2 * rr + 1]));
            tm = fmaxf(tm, __shfl_xor_sync(0xffffffffu, tm, 1));
            tm = fmaxf(tm, __shfl_xor_sync(0xffffffffu, tm, 2));
            float nm = fmaxf(mrow[rr], tm);
            float sum = 0.0f;
#pragma unroll
            for (int ni = 0; ni < 8; ni++) {
                float p0 = __expf(sacc[ni][2 * rr] - nm);
                float p1 = __expf(sacc[ni][2 * rr + 1] - nm);
                sacc[ni][2 * rr] = p0;
                sacc[ni][2 * rr + 1] = p1;
                sum += p0 + p1;
            }
            sum += __shfl_xor_sync(0xffffffffu, sum, 1);
            sum += __shfl_xor_sync(0xffffffffu, sum, 2);
            float f = __expf(mrow[rr] - nm);
            lsum[rr] = lsum[rr] * f + sum;
            mrow[rr] = nm;
#pragma unroll
            for (int ni = 0; ni < 8; ni++) {
                oacc[ni][2 * rr] *= f;
                oacc[ni][2 * rr + 1] *= f;
            }
        }

        // ---- O += P*V (P repacked from sacc registers, 3-term) ----
#pragma unroll
        for (int kc = 0; kc < 4; kc++) {
            unsigned ph[4], pl[4];
            split2(sacc[2 * kc][0],     sacc[2 * kc][1],     ph[0], pl[0]);
            split2(sacc[2 * kc][2],     sacc[2 * kc][3],     ph[1], pl[1]);
            split2(sacc[2 * kc + 1][0], sacc[2 * kc + 1][1], ph[2], pl[2]);
            split2(sacc[2 * kc + 1][2], sacc[2 * kc + 1][3], ph[3], pl[3]);
#pragma unroll
            for (int p = 0; p < 4; p++) {
                unsigned rv = ((kc * 16 + laneRow + qR * 8) * SA + p * 16 + qK * 8) * 2;
                unsigned vh[4], vl[4];
                ldsm4t(vh[0], vh[1], vh[2], vh[3], smem0 + VHo * 2 + sB + rv);
                ldsm4t(vl[0], vl[1], vl[2], vl[3], smem0 + VLo * 2 + sB + rv);
                unsigned vh0[2] = {vh[0], vh[1]}, vh1[2] = {vh[2], vh[3]};
                unsigned vl0[2] = {vl[0], vl[1]}, vl1[2] = {vl[2], vl[3]};
                MMA_BF16(oacc[2 * p],     ph, vh0);
                MMA_BF16(oacc[2 * p],     pl, vh0);
                MMA_BF16(oacc[2 * p],     ph, vl0);
                MMA_BF16(oacc[2 * p + 1], ph, vh1);
                MMA_BF16(oacc[2 * p + 1], pl, vh1);
                MMA_BF16(oacc[2 * p + 1], ph, vl1);
            }
        }
    }

    // epilogue: normalize, split to bf16 hi/lo, write [b,l,d]
#pragma unroll
    for (int rr = 0; rr < 2; rr++) {
        int row = qblk * 128 + w * 16 + g + rr * 8;
        float inv = 1.0f / lsum[rr];
        unsigned* oh = (unsigned*)(g_aoh + (size_t)(b * L_ + row) * D_ + h * HD_);
        unsigned* ol = (unsigned*)(g_aol + (size_t)(b * L_ + row) * D_ + h * HD_);
#pragma unroll
        for (int ni = 0; ni < 8; ni++) {
            unsigned hv, lv;
            split2(oacc[ni][2 * rr] * inv, oacc[ni][2 * rr + 1] * inv, hv, lv);
            oh[ni * 4 + qd] = hv;
            ol[ni * 4 + qd] = lv;
        }
    }
}

// ---------------------------------------------------------------------------
// Launcher
// ---------------------------------------------------------------------------
extern "C" void kernel_launch(void* const* d_in, const int* in_sizes, int n_in,
                              void* d_out, int out_size)
{
    const float* x     = (const float*)d_in[0];
    const float* Wqkv  = (const float*)d_in[1];
    const float* Wproj = (const float*)d_in[2];
    float* out = (float*)d_out;

    float* qkv_p;
    bf16 *xh, *xl, *wqh, *wql, *wph, *wpl, *aoh, *aol;
    cudaGetSymbolAddress((void**)&qkv_p, g_qkv);
    cudaGetSymbolAddress((void**)&xh,  g_xh);  cudaGetSymbolAddress((void**)&xl,  g_xl);
    cudaGetSymbolAddress((void**)&wqh, g_wqh); cudaGetSymbolAddress((void**)&wql, g_wql);
    cudaGetSymbolAddress((void**)&wph, g_wph); cudaGetSymbolAddress((void**)&wpl, g_wpl);
    cudaGetSymbolAddress((void**)&aoh, g_aoh); cudaGetSymbolAddress((void**)&aol, g_aol);

    const int smem_gemm = 8 * STG * sizeof(bf16);                    // 81920
    const int smem_attn = (2 * QTILE + 8 * KTILE) * sizeof(bf16);    // 110592
    cudaFuncSetAttribute(gemm_b3, cudaFuncAttributeMaxDynamicSharedMemorySize, smem_gemm);
    cudaFuncSetAttribute(attn_b3, cudaFuncAttributeMaxDynamicSharedMemorySize, smem_attn);

    // 0) pre-split inputs to bf16 hi/lo
    conv_split<<<(M_ * D_ / 4) / 256, 256>>>(x, xh, xl);
    conv_split<<<(QKV_N * D_ / 4) / 256, 256>>>(Wqkv, wqh, wql);
    conv_split<<<(D_ * D_ / 4) / 256, 256>>>(Wproj, wph, wpl);

    // 1) QKV projection (fp32 out)
    gemm_b3<<<dim3(QKV_N / 128, M_ / 128), 256, smem_gemm>>>(
        xh, xl, wqh, wql, qkv_p, M_, QKV_N, D_);

    // 2) RoPE + split to bf16 hi/lo [b,h,l,hd]
    rope_split<<<(B_ * H_ * L_ * 32) / 256, 256>>>(qkv_p);

    // 3) Attention (128-q tiles, writes bf16 hi/lo attn-out)
    attn_b3<<<dim3(L_ / 128, H_, B_), 256, smem_attn>>>();

    // 4) Output projection (fp32 out)
    gemm_b3<<<dim3(D_ / 128, M_ / 128), 256, smem_gemm>>>(
        aoh, aol, wph, wpl, out, M_, D_, D_);
}